// round 1
// baseline (speedup 1.0000x reference)
#include <cuda_runtime.h>
#include <math.h>

#define SCALE_F 0.125f
#define EPS_F 1e-5f

// ---------------- scratch (device globals; no allocation allowed) ----------------
__device__ float g_heads[2048 * 3072];       // [i*2+b][ q(0..1023) | k(1024..2047) | v(2048..3071) ]
__device__ float g_rk[2047 * 1024];          // r_k [2047][N*DH]
__device__ float g_sc[33554432];             // scores/probs [z=b*16+n][i][j] (32*1024*1024)
__device__ float g_vec[2048 * 1024];         // attention output [i*2+b][n*64+d]
__device__ float g_x[2048 * 1024];           // attn_out = vec @ W_o

// ---------------- generic tiled SGEMM: C[M..][N..] = A @ B ----------------
// grid: (N/64, M/64), block: 16x16. ldc may be NEGATIVE (used for r_bw reversal).
__global__ void sgemm_k(const float* __restrict__ A, const float* __restrict__ B,
                        float* __restrict__ C, int K, int lda, int ldb, int ldc) {
    __shared__ float As[64][16];
    __shared__ float Bs[16][64];
    int tx = threadIdx.x, ty = threadIdx.y;
    int t = ty * 16 + tx;
    int row0 = blockIdx.y * 64, col0 = blockIdx.x * 64;
    float acc[4][4] = {};
    for (int k0 = 0; k0 < K; k0 += 16) {
#pragma unroll
        for (int e = 0; e < 4; e++) {
            int idx = e * 256 + t;
            As[idx >> 4][idx & 15] = A[(long long)(row0 + (idx >> 4)) * lda + k0 + (idx & 15)];
        }
#pragma unroll
        for (int e = 0; e < 4; e++) {
            int idx = e * 256 + t;
            Bs[idx >> 6][idx & 63] = B[(long long)(k0 + (idx >> 6)) * ldb + col0 + (idx & 63)];
        }
        __syncthreads();
#pragma unroll
        for (int kk = 0; kk < 16; kk++) {
            float a[4], bb[4];
#pragma unroll
            for (int r = 0; r < 4; r++) a[r] = As[ty * 4 + r][kk];
#pragma unroll
            for (int c = 0; c < 4; c++) bb[c] = Bs[kk][tx * 4 + c];
#pragma unroll
            for (int r = 0; r < 4; r++)
#pragma unroll
                for (int c = 0; c < 4; c++) acc[r][c] += a[r] * bb[c];
        }
        __syncthreads();
    }
#pragma unroll
    for (int r = 0; r < 4; r++)
#pragma unroll
        for (int c = 0; c < 4; c++)
            C[(long long)(row0 + ty * 4 + r) * ldc + col0 + tx * 4 + c] = acc[r][c];
}

// ---------------- fused score kernel: S = (AC + rel_shift(BD)) * scale, masked ----------------
// rel_shift collapses to: BD[i,j] = sum_d (q[i]+r_r_bias) . r_k[j - i + 1023]
// grid: (16 j-tiles, 16 i-tiles, 32 z=b*16+n), block 16x16. dyn smem = (64*65 + 127*65)*4 B.
__global__ void score_k(const float* __restrict__ heads, const float* __restrict__ rk,
                        const float* __restrict__ rwb, const float* __restrict__ rrb,
                        const unsigned char* __restrict__ mask, float* __restrict__ sc) {
    extern __shared__ float s_dyn[];
    float* qs  = s_dyn;            // 64 x 65
    float* buf = s_dyn + 64 * 65;  // 127 x 65 (k tile uses first 64 rows; band uses 127)
    int tx = threadIdx.x, ty = threadIdx.y, t = ty * 16 + tx;
    int j0 = blockIdx.x * 64, i0 = blockIdx.y * 64;
    int z = blockIdx.z, b = z >> 4, n = z & 15;

    // phase 1: AC = (q + r_w_bias) . k
#pragma unroll
    for (int e = 0; e < 16; e++) {
        int idx = e * 256 + t, ii = idx >> 6, d = idx & 63;
        qs[ii * 65 + d]  = heads[((long long)(i0 + ii) * 2 + b) * 3072 + n * 64 + d] + rwb[n * 64 + d];
        buf[ii * 65 + d] = heads[((long long)(j0 + ii) * 2 + b) * 3072 + 1024 + n * 64 + d];
    }
    __syncthreads();
    float acc[4][4] = {};
#pragma unroll 4
    for (int d = 0; d < 64; d++) {
        float a[4], bb[4];
#pragma unroll
        for (int r = 0; r < 4; r++) a[r] = qs[(ty * 4 + r) * 65 + d];
#pragma unroll
        for (int c = 0; c < 4; c++) bb[c] = buf[(tx * 4 + c) * 65 + d];
#pragma unroll
        for (int r = 0; r < 4; r++)
#pragma unroll
            for (int c = 0; c < 4; c++) acc[r][c] += a[r] * bb[c];
    }
    __syncthreads();

    // phase 2: BD with diagonal band of r_k. jr = j - i + 1023; band row = (jc - ir) + 63
    int jr0 = j0 - i0 + 960;  // (j0+0) - (i0+63) + 1023
#pragma unroll
    for (int e = 0; e < 16; e++) {
        int idx = e * 256 + t, ii = idx >> 6, d = idx & 63;
        qs[ii * 65 + d] = heads[((long long)(i0 + ii) * 2 + b) * 3072 + n * 64 + d] + rrb[n * 64 + d];
    }
#pragma unroll
    for (int e = 0; e < 32; e++) {
        int idx = e * 256 + t;
        if (idx < 127 * 64) {
            int rr = idx >> 6, d = idx & 63;
            buf[rr * 65 + d] = rk[(long long)(jr0 + rr) * 1024 + n * 64 + d];
        }
    }
    __syncthreads();
#pragma unroll 2
    for (int d = 0; d < 64; d++) {
        float a2[4];
#pragma unroll
        for (int r = 0; r < 4; r++) a2[r] = qs[(ty * 4 + r) * 65 + d];
#pragma unroll
        for (int r = 0; r < 4; r++)
#pragma unroll
            for (int c = 0; c < 4; c++)
                acc[r][c] += a2[r] * buf[(63 + tx * 4 + c - (ty * 4 + r)) * 65 + d];
    }

#pragma unroll
    for (int r = 0; r < 4; r++)
#pragma unroll
        for (int c = 0; c < 4; c++) {
            int i = i0 + ty * 4 + r, j = j0 + tx * 4 + c;
            float s = acc[r][c] * SCALE_F;
            if (mask[j * 2 + b]) s = -1e30f;
            sc[((long long)z << 20) + ((long long)i << 10) + j] = s;
        }
}

// ---------------- softmax over j (row length 1024). grid (1024, 32), 256 threads ----------------
__global__ void softmax_k(float* __restrict__ sc) {
    __shared__ float sm[8];
    int i = blockIdx.x, z = blockIdx.y, t = threadIdx.x;
    float* row = sc + ((long long)z << 20) + ((long long)i << 10);
    float v[4];
    float m = -3.4e38f;
#pragma unroll
    for (int e = 0; e < 4; e++) { v[e] = row[e * 256 + t]; m = fmaxf(m, v[e]); }
#pragma unroll
    for (int o = 16; o; o >>= 1) m = fmaxf(m, __shfl_xor_sync(0xffffffffu, m, o));
    if ((t & 31) == 0) sm[t >> 5] = m;
    __syncthreads();
    m = sm[t & 7];
#pragma unroll
    for (int o = 4; o; o >>= 1) m = fmaxf(m, __shfl_xor_sync(0xffffffffu, m, o));
    float s = 0.f;
#pragma unroll
    for (int e = 0; e < 4; e++) { v[e] = expf(v[e] - m); s += v[e]; }
#pragma unroll
    for (int o = 16; o; o >>= 1) s += __shfl_xor_sync(0xffffffffu, s, o);
    __syncthreads();
    if ((t & 31) == 0) sm[t >> 5] = s;
    __syncthreads();
    s = sm[t & 7];
#pragma unroll
    for (int o = 4; o; o >>= 1) s += __shfl_xor_sync(0xffffffffu, s, o);
    float inv = 1.0f / s;
#pragma unroll
    for (int e = 0; e < 4; e++) row[e * 256 + t] = v[e] * inv;
}

// ---------------- vec = prob @ v. grid (16 i-tiles, 32 z), block 16x16 ----------------
__global__ void pv_k(const float* __restrict__ sc, const float* __restrict__ heads,
                     float* __restrict__ vec) {
    __shared__ float ps[64 * 65];
    __shared__ float vs[64 * 65];
    int tx = threadIdx.x, ty = threadIdx.y, t = ty * 16 + tx;
    int i0 = blockIdx.x * 64;
    int z = blockIdx.y, b = z >> 4, n = z & 15;
    const float* prow = sc + ((long long)z << 20);
    float acc[4][4] = {};
    for (int jb = 0; jb < 1024; jb += 64) {
#pragma unroll
        for (int e = 0; e < 16; e++) {
            int idx = e * 256 + t, a_ = idx >> 6, d = idx & 63;
            ps[a_ * 65 + d] = prow[((long long)(i0 + a_) << 10) + jb + d];
            vs[a_ * 65 + d] = heads[((long long)(jb + a_) * 2 + b) * 3072 + 2048 + n * 64 + d];
        }
        __syncthreads();
#pragma unroll 4
        for (int jj = 0; jj < 64; jj++) {
            float a[4], bv[4];
#pragma unroll
            for (int r = 0; r < 4; r++) a[r] = ps[(ty * 4 + r) * 65 + jj];
#pragma unroll
            for (int c = 0; c < 4; c++) bv[c] = vs[jj * 65 + tx * 4 + c];
#pragma unroll
            for (int r = 0; r < 4; r++)
#pragma unroll
                for (int c = 0; c < 4; c++) acc[r][c] += a[r] * bv[c];
        }
        __syncthreads();
    }
#pragma unroll
    for (int r = 0; r < 4; r++)
#pragma unroll
        for (int c = 0; c < 4; c++)
            vec[((long long)(i0 + ty * 4 + r) * 2 + b) * 1024 + n * 64 + tx * 4 + c] = acc[r][c];
}

// ---------------- residual + LayerNorm. grid 2048 rows, 256 threads ----------------
__global__ void ln_k(const float* __restrict__ w, const float* __restrict__ xb,
                     const float* __restrict__ g, const float* __restrict__ bb,
                     float* __restrict__ out) {
    __shared__ float sm[16];
    int row = blockIdx.x, t = threadIdx.x;
    const float* wr = w + (long long)row * 1024;
    const float* xr = xb + (long long)row * 1024;
    float loc[4], s = 0.f, sq = 0.f;
#pragma unroll
    for (int e = 0; e < 4; e++) {
        float x = wr[e * 256 + t] + xr[e * 256 + t];
        loc[e] = x; s += x; sq += x * x;
    }
#pragma unroll
    for (int o = 16; o; o >>= 1) {
        s += __shfl_xor_sync(0xffffffffu, s, o);
        sq += __shfl_xor_sync(0xffffffffu, sq, o);
    }
    if ((t & 31) == 0) { sm[t >> 5] = s; sm[8 + (t >> 5)] = sq; }
    __syncthreads();
    s = sm[t & 7]; sq = sm[8 + (t & 7)];
#pragma unroll
    for (int o = 4; o; o >>= 1) {
        s += __shfl_xor_sync(0xffffffffu, s, o);
        sq += __shfl_xor_sync(0xffffffffu, sq, o);
    }
    float mu = s * (1.0f / 1024.0f);
    float var = sq * (1.0f / 1024.0f) - mu * mu;
    float rstd = rsqrtf(var + EPS_F);
#pragma unroll
    for (int e = 0; e < 4; e++) {
        int c = e * 256 + t;
        out[(long long)row * 1024 + c] = (loc[e] - mu) * rstd * g[c] + bb[c];
    }
}

// ---------------- launch ----------------
extern "C" void kernel_launch(void* const* d_in, const int* in_sizes, int n_in,
                              void* d_out, int out_size) {
    const float* w    = (const float*)d_in[0];   // [1024,2,1024]
    const float* r    = (const float*)d_in[1];   // [1024,1024]
    const float* rwb  = (const float*)d_in[2];   // [16,64]
    const float* rrb  = (const float*)d_in[3];   // [16,64]
    const unsigned char* mask = (const unsigned char*)d_in[4];  // [1024,2] bool
    const float* Wqkv = (const float*)d_in[5];   // [1024,3072]
    const float* Wrfw = (const float*)d_in[6];   // [1024,1024]
    const float* Wrbw = (const float*)d_in[7];   // [1024,1024]
    const float* Wo   = (const float*)d_in[8];   // [1024,1024]
    const float* lng  = (const float*)d_in[9];   // [1024]
    const float* lnb  = (const float*)d_in[10];  // [1024]
    float* out = (float*)d_out;

    float *heads, *rk, *sc, *vec, *xb;
    cudaGetSymbolAddress((void**)&heads, g_heads);
    cudaGetSymbolAddress((void**)&rk, g_rk);
    cudaGetSymbolAddress((void**)&sc, g_sc);
    cudaGetSymbolAddress((void**)&vec, g_vec);
    cudaGetSymbolAddress((void**)&xb, g_x);

    dim3 blk(16, 16);

    // heads = w2d @ W_qkv    [2048,1024]@[1024,3072]
    sgemm_k<<<dim3(3072 / 64, 2048 / 64), blk>>>(w, Wqkv, heads, 1024, 1024, 3072, 3072);
    // r_bw GEMM written REVERSED into r_k rows 2046..1023 (negative ldc).
    // Row 1023 gets a bogus value here, overwritten by the r_fw GEMM next.
    sgemm_k<<<dim3(16, 16), blk>>>(r, Wrbw, rk + 2046 * 1024, 1024, 1024, 1024, -1024);
    // r_fw GEMM into r_k rows 0..1023
    sgemm_k<<<dim3(16, 16), blk>>>(r, Wrfw, rk, 1024, 1024, 1024, 1024);

    // fused AC + rel-shifted BD scores
    int score_smem = (64 * 65 + 127 * 65) * (int)sizeof(float);  // 49660 B
    cudaFuncSetAttribute(score_k, cudaFuncAttributeMaxDynamicSharedMemorySize, score_smem);
    score_k<<<dim3(16, 16, 32), blk, score_smem>>>(heads, rk, rwb, rrb, mask, sc);

    softmax_k<<<dim3(1024, 32), 256>>>(sc);

    pv_k<<<dim3(16, 32), blk>>>(sc, heads, vec);

    // attn_out = vec @ W_o
    sgemm_k<<<dim3(16, 32), blk>>>(vec, Wo, xb, 1024, 1024, 1024, 1024);

    // x = w + attn_out; LayerNorm
    ln_k<<<2048, 256>>>(w, xb, lng, lnb, out);
}

// round 4
// speedup vs baseline: 2.9924x; 2.9924x over previous
#include <cuda_runtime.h>
#include <math.h>

#define SCALE_F 0.125f
#define EPS_F 1e-5f

// ---------------- scratch (device globals) ----------------
__device__ float g_q1[32 * 1024 * 64];   // q + r_w_bias, [z][i][64]
__device__ float g_q2[32 * 1024 * 64];   // q + r_r_bias
__device__ float g_kk[32 * 1024 * 64];   // k heads
__device__ float g_vv[32 * 1024 * 64];   // v heads
__device__ float g_rk[2048 * 1024];      // r_k padded to 2048 rows (row 2047 zeroed)
__device__ float g_bd[67108864];         // BD [z][1024][2048] (band-only written)
__device__ float g_sc[33554432];         // AC then probs [z][i][j]
__device__ float g_vec[2048 * 1024];     // attn vec [(i*2+b)][n*64+d]
__device__ float g_x[2048 * 1024];       // vec @ W_o

// ---------------- helpers ----------------
__device__ __forceinline__ void cp16(float* s, const float* g) {
    unsigned a = (unsigned)__cvta_generic_to_shared(s);
    asm volatile("cp.async.cg.shared.global [%0], [%1], 16;\n" ::"r"(a), "l"(g));
}
__device__ __forceinline__ int swzA(int r, int col) {  // 16-float rows
    return r * 16 + (((col >> 2) ^ ((r >> 1) & 3)) << 2) + (col & 3);
}
__device__ __forceinline__ int swzB(int k, int n) {    // 64-float rows
    return k * 64 + (((n >> 2) ^ ((2 * k) & 15)) << 2) + (n & 3);
}
#define MMA_TF32(c, a, b)                                                          \
    asm volatile(                                                                  \
        "mma.sync.aligned.m16n8k8.row.col.f32.tf32.tf32.f32 "                      \
        "{%0,%1,%2,%3},{%4,%5,%6,%7},{%8,%9},{%0,%1,%2,%3};"                       \
        : "+f"(c[0]), "+f"(c[1]), "+f"(c[2]), "+f"(c[3])                           \
        : "r"(a[0]), "r"(a[1]), "r"(a[2]), "r"(a[3]), "r"(b[0]), "r"(b[1]))

// ---------------- tf32 tensor-core GEMM ----------------
// C[M][N] = A[M][K] @ B.  BNK=1: B given [N][K] row-major (i.e. C = A@B^T).
// EPI: 0 plain store, 1 PV scatter, 2 QKV head scatter.
// BOFF=1 (BD kernel): per-head B offset = (z&15)*64, and diagonal-band col
// remap col0 = 896 - row0 + bx*64 (only the band softmax reads is computed).
template <int BNK, int EPI, int BOFF>
__global__ __launch_bounds__(256) void gemm_k(
    const float* __restrict__ A, const float* __restrict__ B, float* __restrict__ C,
    int M, int N, int K, int lda, int ldb, int ldc,
    long long strA, long long strB, long long strC,
    const float* __restrict__ bias1, const float* __restrict__ bias2,
    float* __restrict__ o2, float* __restrict__ o3, float* __restrict__ o4) {
    __shared__ float sm[2 * 3072];
    int t = threadIdx.x, lane = t & 31, lq = t & 3;
    int z = blockIdx.z;
    A += z * strA;
    if (BOFF) B += (long long)(z & 15) * 64; else B += z * strB;
    C += z * strC;
    int row0 = blockIdx.y * 128;
    int col0 = BOFF ? (896 - row0 + blockIdx.x * 64) : blockIdx.x * 64;
    int warp = t >> 5, wm = warp >> 1, wn = warp & 1;

    float acc[2][4][4] = {};

    auto load_tile = [&](int kt, int st) {
        float* sA = sm + st * 3072;
        float* sB = sA + 2048;
        int k0 = kt * 16;
#pragma unroll
        for (int e = 0; e < 2; e++) {
            int idx = e * 256 + t, r = idx >> 2, c4 = idx & 3;
            cp16(sA + r * 16 + ((c4 ^ ((r >> 1) & 3)) << 2),
                 A + (long long)(row0 + r) * lda + k0 + (c4 << 2));
        }
        if (BNK) {
            int r = t >> 2, c4 = t & 3;
            cp16(sB + r * 16 + ((c4 ^ ((r >> 1) & 3)) << 2),
                 B + (long long)(col0 + r) * ldb + k0 + (c4 << 2));
        } else {
            int kr = t >> 4, c4 = t & 15;
            cp16(sB + kr * 64 + ((c4 ^ ((2 * kr) & 15)) << 2),
                 B + (long long)(k0 + kr) * ldb + col0 + (c4 << 2));
        }
        asm volatile("cp.async.commit_group;\n");
    };

    load_tile(0, 0);
    int KT = K >> 4;
    for (int kt = 0; kt < KT; kt++) {
        int st = kt & 1;
        if (kt + 1 < KT) {
            load_tile(kt + 1, st ^ 1);
            asm volatile("cp.async.wait_group 1;\n");
        } else {
            asm volatile("cp.async.wait_group 0;\n");
        }
        __syncthreads();
        float* sA = sm + st * 3072;
        float* sB = sA + 2048;
#pragma unroll
        for (int ks = 0; ks < 16; ks += 8) {
            unsigned af[2][4], bf[4][2];
#pragma unroll
            for (int mt = 0; mt < 2; mt++) {
                int r = wm * 32 + mt * 16 + (lane >> 2);
                af[mt][0] = __float_as_uint(sA[swzA(r, ks + lq)]);
                af[mt][1] = __float_as_uint(sA[swzA(r + 8, ks + lq)]);
                af[mt][2] = __float_as_uint(sA[swzA(r, ks + 4 + lq)]);
                af[mt][3] = __float_as_uint(sA[swzA(r + 8, ks + 4 + lq)]);
            }
#pragma unroll
            for (int nt = 0; nt < 4; nt++) {
                int n = wn * 32 + nt * 8 + (lane >> 2);
                if (BNK) {
                    bf[nt][0] = __float_as_uint(sB[swzA(n, ks + lq)]);
                    bf[nt][1] = __float_as_uint(sB[swzA(n, ks + 4 + lq)]);
                } else {
                    bf[nt][0] = __float_as_uint(sB[swzB(ks + lq, n)]);
                    bf[nt][1] = __float_as_uint(sB[swzB(ks + 4 + lq, n)]);
                }
            }
#pragma unroll
            for (int mt = 0; mt < 2; mt++)
#pragma unroll
                for (int nt = 0; nt < 4; nt++) MMA_TF32(acc[mt][nt], af[mt], bf[nt]);
        }
        __syncthreads();
    }

    // epilogue
#pragma unroll
    for (int mt = 0; mt < 2; mt++)
#pragma unroll
        for (int nt = 0; nt < 4; nt++) {
            int r0 = row0 + wm * 32 + mt * 16 + (lane >> 2);
            int cb = col0 + wn * 32 + nt * 8 + 2 * lq;
#pragma unroll
            for (int e = 0; e < 4; e++) {
                int rr = r0 + (e >> 1) * 8;
                int cc = cb + (e & 1);
                float v = acc[mt][nt][e];
                if (EPI == 0) {
                    C[(long long)rr * (long long)ldc + cc] = v;
                } else if (EPI == 1) {
                    int bb = z >> 4, nn = z & 15;
                    C[(((long long)(rr * 2 + bb)) << 10) + (nn << 6) + cc] = v;
                } else {
                    int i = rr >> 1, bb = rr & 1;
                    int sec = cc >> 10, c1 = cc & 1023, n = c1 >> 6, d = c1 & 63;
                    long long idx = (((long long)(bb * 16 + n)) << 16) + (i << 6) + d;
                    if (sec == 0) {
                        C[idx] = v + bias1[c1];   // q1
                        o2[idx] = v + bias2[c1];  // q2
                    } else if (sec == 1) {
                        o3[idx] = v;              // k
                    } else {
                        o4[idx] = v;              // v
                    }
                }
            }
        }
}

// ---------------- zero pad row of rk ----------------
__global__ void zero_k(float* p) { p[blockIdx.x * 256 + threadIdx.x] = 0.0f; }

// ---------------- fused score assemble + softmax ----------------
// S[i][j] = (AC[z][i][j] + BD[z][i][1023-i+j]) * scale, masked; softmax over j; write probs.
__global__ void softmax_k(const float* __restrict__ bd, float* __restrict__ sc,
                          const unsigned char* __restrict__ mask) {
    __shared__ float smr[8];
    int i = blockIdx.x, z = blockIdx.y, t = threadIdx.x, b = z >> 4;
    float* row = sc + ((long long)z << 20) + ((long long)i << 10);
    const float* bdr = bd + ((long long)z << 21) + ((long long)i << 11) + (1023 - i);
    float v[4];
    float m = -3.4e38f;
#pragma unroll
    for (int e = 0; e < 4; e++) {
        int j = e * 256 + t;
        float s = (row[j] + bdr[j]) * SCALE_F;
        if (mask[j * 2 + b]) s = -1e30f;
        v[e] = s;
        m = fmaxf(m, s);
    }
#pragma unroll
    for (int o = 16; o; o >>= 1) m = fmaxf(m, __shfl_xor_sync(0xffffffffu, m, o));
    if ((t & 31) == 0) smr[t >> 5] = m;
    __syncthreads();
    m = smr[t & 7];
#pragma unroll
    for (int o = 4; o; o >>= 1) m = fmaxf(m, __shfl_xor_sync(0xffffffffu, m, o));
    float s = 0.f;
#pragma unroll
    for (int e = 0; e < 4; e++) { v[e] = expf(v[e] - m); s += v[e]; }
#pragma unroll
    for (int o = 16; o; o >>= 1) s += __shfl_xor_sync(0xffffffffu, s, o);
    __syncthreads();
    if ((t & 31) == 0) smr[t >> 5] = s;
    __syncthreads();
    s = smr[t & 7];
#pragma unroll
    for (int o = 4; o; o >>= 1) s += __shfl_xor_sync(0xffffffffu, s, o);
    float inv = 1.0f / s;
#pragma unroll
    for (int e = 0; e < 4; e++) row[e * 256 + t] = v[e] * inv;
}

// ---------------- residual + LayerNorm ----------------
__global__ void ln_k(const float* __restrict__ w, const float* __restrict__ xb,
                     const float* __restrict__ g, const float* __restrict__ bb,
                     float* __restrict__ out) {
    __shared__ float smr[16];
    int row = blockIdx.x, t = threadIdx.x;
    const float* wr = w + (long long)row * 1024;
    const float* xr = xb + (long long)row * 1024;
    float loc[4], s = 0.f, sq = 0.f;
#pragma unroll
    for (int e = 0; e < 4; e++) {
        float x = wr[e * 256 + t] + xr[e * 256 + t];
        loc[e] = x; s += x; sq += x * x;
    }
#pragma unroll
    for (int o = 16; o; o >>= 1) {
        s += __shfl_xor_sync(0xffffffffu, s, o);
        sq += __shfl_xor_sync(0xffffffffu, sq, o);
    }
    if ((t & 31) == 0) { smr[t >> 5] = s; smr[8 + (t >> 5)] = sq; }
    __syncthreads();
    s = smr[t & 7]; sq = smr[8 + (t & 7)];
#pragma unroll
    for (int o = 4; o; o >>= 1) {
        s += __shfl_xor_sync(0xffffffffu, s, o);
        sq += __shfl_xor_sync(0xffffffffu, sq, o);
    }
    float mu = s * (1.0f / 1024.0f);
    float var = sq * (1.0f / 1024.0f) - mu * mu;
    float rstd = rsqrtf(var + EPS_F);
#pragma unroll
    for (int e = 0; e < 4; e++) {
        int c = e * 256 + t;
        out[(long long)row * 1024 + c] = (loc[e] - mu) * rstd * g[c] + bb[c];
    }
}

// ---------------- launch ----------------
extern "C" void kernel_launch(void* const* d_in, const int* in_sizes, int n_in,
                              void* d_out, int out_size) {
    const float* w    = (const float*)d_in[0];
    const float* r    = (const float*)d_in[1];
    const float* rwb  = (const float*)d_in[2];
    const float* rrb  = (const float*)d_in[3];
    const unsigned char* mask = (const unsigned char*)d_in[4];
    const float* Wqkv = (const float*)d_in[5];
    const float* Wrfw = (const float*)d_in[6];
    const float* Wrbw = (const float*)d_in[7];
    const float* Wo   = (const float*)d_in[8];
    const float* lng  = (const float*)d_in[9];
    const float* lnb  = (const float*)d_in[10];
    float* out = (float*)d_out;

    float *q1, *q2, *kk, *vv, *rk, *bd, *sc, *vec, *xb;
    cudaGetSymbolAddress((void**)&q1, g_q1);
    cudaGetSymbolAddress((void**)&q2, g_q2);
    cudaGetSymbolAddress((void**)&kk, g_kk);
    cudaGetSymbolAddress((void**)&vv, g_vv);
    cudaGetSymbolAddress((void**)&rk, g_rk);
    cudaGetSymbolAddress((void**)&bd, g_bd);
    cudaGetSymbolAddress((void**)&sc, g_sc);
    cudaGetSymbolAddress((void**)&vec, g_vec);
    cudaGetSymbolAddress((void**)&xb, g_x);

    // zero pad row 2047 of rk
    zero_k<<<4, 256>>>(rk + 2047 * 1024);

    // QKV GEMM with fused head scatter (+biases) into q1/q2/kk/vv
    gemm_k<0, 2, 0><<<dim3(48, 16, 1), 256>>>(w, Wqkv, q1, 2048, 3072, 1024,
                                              1024, 3072, 0, 0, 0, 0,
                                              rwb, rrb, q2, kk, vv);
    // r_bw reversed into rk rows 2046..1023 (row 1023 then overwritten by r_fw)
    gemm_k<0, 0, 0><<<dim3(16, 8, 1), 256>>>(r, Wrbw, rk + 2046 * 1024, 1024, 1024, 1024,
                                             1024, 1024, -1024, 0, 0, 0,
                                             0, 0, 0, 0, 0);
    gemm_k<0, 0, 0><<<dim3(16, 8, 1), 256>>>(r, Wrfw, rk, 1024, 1024, 1024,
                                             1024, 1024, 1024, 0, 0, 0,
                                             0, 0, 0, 0, 0);
    // AC[z] = Q1_z @ K_z^T  -> sc
    gemm_k<1, 0, 0><<<dim3(16, 8, 32), 256>>>(q1, kk, sc, 1024, 1024, 64,
                                              64, 64, 1024, 65536, 65536, 1LL << 20,
                                              0, 0, 0, 0, 0);
    // BD[z] band = Q2_z @ rk^T, only the 18 col-tiles softmax reads
    gemm_k<1, 0, 1><<<dim3(18, 8, 32), 256>>>(q2, rk, bd, 1024, 2048, 64,
                                              64, 1024, 2048, 65536, 0, 1LL << 21,
                                              0, 0, 0, 0, 0);
    // fused scale + rel-shift gather + mask + softmax (probs in sc)
    softmax_k<<<dim3(1024, 32), 256>>>(bd, sc, mask);
    // vec[z] = P_z @ V_z with scatter to [(i*2+b)][n*64+d]
    gemm_k<0, 1, 0><<<dim3(1, 8, 32), 256>>>(sc, vv, vec, 1024, 64, 1024,
                                             1024, 64, 0, 1LL << 20, 65536, 0,
                                             0, 0, 0, 0, 0);
    // attn_out = vec @ W_o
    gemm_k<0, 0, 0><<<dim3(16, 16, 1), 256>>>(vec, Wo, xb, 2048, 1024, 1024,
                                              1024, 1024, 1024, 0, 0, 0,
                                              0, 0, 0, 0, 0);
    // residual + LN
    ln_k<<<2048, 256>>>(w, xb, lng, lnb, out);
}

// round 5
// speedup vs baseline: 3.0021x; 1.0033x over previous
#include <cuda_runtime.h>
#include <math.h>

#define SCALE_F 0.125f
#define EPS_F 1e-5f

// ---------------- scratch (device globals) ----------------
__device__ float g_q1[32 * 1024 * 64];   // q + r_w_bias, [z][i][64]
__device__ float g_q2[32 * 1024 * 64];   // q + r_r_bias
__device__ float g_kk[32 * 1024 * 64];   // k heads
__device__ float g_vv[32 * 1024 * 64];   // v heads
__device__ float g_rk[2048 * 1024];      // r_k padded to 2048 rows (row 2047 zeroed)
__device__ float g_bd[67108864];         // BD [z][1024][2048] (band-only written)
__device__ float g_vec[2048 * 1024];     // attn vec [(i*2+b)][n*64+d]
__device__ float g_x[2048 * 1024];       // vec @ W_o

// ---------------- helpers ----------------
__device__ __forceinline__ void cp16(float* s, const float* g) {
    unsigned a = (unsigned)__cvta_generic_to_shared(s);
    asm volatile("cp.async.cg.shared.global [%0], [%1], 16;\n" ::"r"(a), "l"(g));
}
__device__ __forceinline__ int swzA(int r, int col) {  // 16-float rows
    return r * 16 + (((col >> 2) ^ ((r >> 1) & 3)) << 2) + (col & 3);
}
__device__ __forceinline__ int swzB(int k, int n) {    // 64-float rows
    return k * 64 + (((n >> 2) ^ ((2 * k) & 15)) << 2) + (n & 3);
}
#define MMA_TF32(c, a, b)                                                          \
    asm volatile(                                                                  \
        "mma.sync.aligned.m16n8k8.row.col.f32.tf32.tf32.f32 "                      \
        "{%0,%1,%2,%3},{%4,%5,%6,%7},{%8,%9},{%0,%1,%2,%3};"                       \
        : "+f"(c[0]), "+f"(c[1]), "+f"(c[2]), "+f"(c[3])                           \
        : "r"(a[0]), "r"(a[1]), "r"(a[2]), "r"(a[3]), "r"(b[0]), "r"(b[1]))

// ---------------- tf32 tensor-core GEMM ----------------
// C[M][N] = A[M][K] @ B.  BNK=1: B given [N][K] row-major (C = A@B^T).
// EPI: 0 plain store, 2 QKV head scatter.
// BOFF=1 (BD): per-head B offset (z&15)*64 + diagonal band col remap.
// BOFF=2 (RK): bx>=16 switches to B2=bias1 (W_r_bw), C2=o2, ldc=-1024.
template <int BNK, int EPI, int BOFF>
__global__ __launch_bounds__(256) void gemm_k(
    const float* __restrict__ A, const float* __restrict__ B, float* __restrict__ C,
    int M, int N, int K, int lda, int ldb, int ldc,
    long long strA, long long strB, long long strC,
    const float* __restrict__ bias1, const float* __restrict__ bias2,
    float* __restrict__ o2, float* __restrict__ o3, float* __restrict__ o4) {
    __shared__ float sm[2 * 3072];
    int t = threadIdx.x, lane = t & 31, lq = t & 3;
    int z = blockIdx.z;
    A += z * strA;
    if (BOFF == 1) B += (long long)(z & 15) * 64; else B += z * strB;
    C += z * strC;
    int row0 = blockIdx.y * 128;
    int col0;
    if (BOFF == 1) col0 = 896 - row0 + blockIdx.x * 64;
    else if (BOFF == 2) col0 = (blockIdx.x & 15) * 64;
    else col0 = blockIdx.x * 64;
    if (BOFF == 2 && blockIdx.x >= 16) { B = bias1; C = o2; ldc = -1024; }
    int warp = t >> 5, wm = warp >> 1, wn = warp & 1;

    float acc[2][4][4] = {};

    auto load_tile = [&](int kt, int st) {
        float* sA = sm + st * 3072;
        float* sB = sA + 2048;
        int k0 = kt * 16;
#pragma unroll
        for (int e = 0; e < 2; e++) {
            int idx = e * 256 + t, r = idx >> 2, c4 = idx & 3;
            cp16(sA + r * 16 + ((c4 ^ ((r >> 1) & 3)) << 2),
                 A + (long long)(row0 + r) * lda + k0 + (c4 << 2));
        }
        if (BNK) {
            int r = t >> 2, c4 = t & 3;
            cp16(sB + r * 16 + ((c4 ^ ((r >> 1) & 3)) << 2),
                 B + (long long)(col0 + r) * ldb + k0 + (c4 << 2));
        } else {
            int kr = t >> 4, c4 = t & 15;
            cp16(sB + kr * 64 + ((c4 ^ ((2 * kr) & 15)) << 2),
                 B + (long long)(k0 + kr) * ldb + col0 + (c4 << 2));
        }
        asm volatile("cp.async.commit_group;\n");
    };

    load_tile(0, 0);
    int KT = K >> 4;
    for (int kt = 0; kt < KT; kt++) {
        int st = kt & 1;
        if (kt + 1 < KT) {
            load_tile(kt + 1, st ^ 1);
            asm volatile("cp.async.wait_group 1;\n");
        } else {
            asm volatile("cp.async.wait_group 0;\n");
        }
        __syncthreads();
        float* sA = sm + st * 3072;
        float* sB = sA + 2048;
#pragma unroll
        for (int ks = 0; ks < 16; ks += 8) {
            unsigned af[2][4], bf[4][2];
#pragma unroll
            for (int mt = 0; mt < 2; mt++) {
                int r = wm * 32 + mt * 16 + (lane >> 2);
                af[mt][0] = __float_as_uint(sA[swzA(r, ks + lq)]);
                af[mt][1] = __float_as_uint(sA[swzA(r + 8, ks + lq)]);
                af[mt][2] = __float_as_uint(sA[swzA(r, ks + 4 + lq)]);
                af[mt][3] = __float_as_uint(sA[swzA(r + 8, ks + 4 + lq)]);
            }
#pragma unroll
            for (int nt = 0; nt < 4; nt++) {
                int n = wn * 32 + nt * 8 + (lane >> 2);
                if (BNK) {
                    bf[nt][0] = __float_as_uint(sB[swzA(n, ks + lq)]);
                    bf[nt][1] = __float_as_uint(sB[swzA(n, ks + 4 + lq)]);
                } else {
                    bf[nt][0] = __float_as_uint(sB[swzB(ks + lq, n)]);
                    bf[nt][1] = __float_as_uint(sB[swzB(ks + 4 + lq, n)]);
                }
            }
#pragma unroll
            for (int mt = 0; mt < 2; mt++)
#pragma unroll
                for (int nt = 0; nt < 4; nt++) MMA_TF32(acc[mt][nt], af[mt], bf[nt]);
        }
        __syncthreads();
    }

#pragma unroll
    for (int mt = 0; mt < 2; mt++)
#pragma unroll
        for (int nt = 0; nt < 4; nt++) {
            int r0 = row0 + wm * 32 + mt * 16 + (lane >> 2);
            int cb = col0 + wn * 32 + nt * 8 + 2 * lq;
#pragma unroll
            for (int e = 0; e < 4; e++) {
                int rr = r0 + (e >> 1) * 8;
                int cc = cb + (e & 1);
                float v = acc[mt][nt][e];
                if (EPI == 0) {
                    C[(long long)rr * (long long)ldc + cc] = v;
                } else {
                    int i = rr >> 1, bb = rr & 1;
                    int sec = cc >> 10, c1 = cc & 1023, n = c1 >> 6, d = c1 & 63;
                    long long idx = (((long long)(bb * 16 + n)) << 16) + (i << 6) + d;
                    if (sec == 0) {
                        C[idx] = v + bias1[c1];   // q1
                        o2[idx] = v + bias2[c1];  // q2
                    } else if (sec == 1) {
                        o3[idx] = v;              // k
                    } else {
                        o4[idx] = v;              // v
                    }
                }
            }
        }
}

// ---------------- zero pad row of rk ----------------
__global__ void zero_k(float* p) { p[blockIdx.x * 256 + threadIdx.x] = 0.0f; }

// ---------------- flash kernel: S = Q1·K^T + BD_band, mask, online softmax, P·V ----------------
// grid (8 i-tiles, 32 z), 256 threads (8 warps). Each warp owns 16 rows.
#define FSTR 68
__global__ __launch_bounds__(256) void flash_k(
    const float* __restrict__ q1, const float* __restrict__ kk,
    const float* __restrict__ vv, const float* __restrict__ bd,
    const unsigned char* __restrict__ mask, float* __restrict__ vec) {
    extern __shared__ float fs[];
    float* sQ = fs;                       // 128 x 68
    float* sP = sQ + 128 * FSTR;          // 128 x 68
    float* sK = sP + 128 * FSTR;          // 2 x 64 x 68
    float* sV = sK + 2 * 64 * FSTR;       // 2 x 64 x 64 (swzB)
    float* sMask = sV + 2 * 64 * 64;      // 1024 flags

    int t = threadIdx.x, lane = t & 31, warp = t >> 5;
    int lq = lane & 3, lr = lane >> 2;
    int i0 = blockIdx.x * 128, z = blockIdx.y, b = z >> 4, nh = z & 15;
    const float* Qz = q1 + ((long long)z << 16);
    const float* Kz = kk + ((long long)z << 16);
    const float* Vz = vv + ((long long)z << 16);
    const float* bdz = bd + ((long long)z << 21);

    // mask flags
    for (int e = t; e < 1024; e += 256) sMask[e] = mask[e * 2 + b] ? 1.0f : 0.0f;

    // load Q tile (part of cp.async group 0)
#pragma unroll
    for (int e = 0; e < 8; e++) {
        int idx = e * 256 + t, rr = idx >> 4, c4 = idx & 15;
        cp16(sQ + rr * FSTR + c4 * 4, Qz + (long long)(i0 + rr) * 64 + c4 * 4);
    }
    auto loadKV = [&](int jt, int bufi) {
        float* dK = sK + bufi * 64 * FSTR;
        float* dV = sV + bufi * 64 * 64;
        int j0 = jt * 64;
#pragma unroll
        for (int e = 0; e < 4; e++) {
            int idx = e * 256 + t, rr = idx >> 4, c4 = idx & 15;
            cp16(dK + rr * FSTR + c4 * 4, Kz + (long long)(j0 + rr) * 64 + c4 * 4);
            cp16(dV + rr * 64 + (((c4 ^ ((2 * rr) & 15))) << 2),
                 Vz + (long long)(j0 + rr) * 64 + c4 * 4);
        }
        asm volatile("cp.async.commit_group;\n");
    };
    loadKV(0, 0);  // group 0 (with Q)
    loadKV(1, 1);  // group 1

    float mA = -3.4e38f, mB = -3.4e38f, lA = 0.f, lB = 0.f;
    float O[8][4] = {};
    int rb = warp * 16 + lr;       // local row for c0,c1 (rb+8 for c2,c3)
    int rowA = i0 + rb;            // global i

    for (int jt = 0; jt < 16; jt++) {
        int buf = jt & 1;
        asm volatile("cp.async.wait_group 1;\n");
        __syncthreads();

        // ---- S = Q1 @ K^T ----
        float* cK = sK + buf * 64 * FSTR;
        float S[8][4] = {};
#pragma unroll
        for (int kc = 0; kc < 8; kc++) {
            int k0 = kc * 8;
            unsigned a[4];
            a[0] = __float_as_uint(sQ[rb * FSTR + k0 + lq]);
            a[1] = __float_as_uint(sQ[(rb + 8) * FSTR + k0 + lq]);
            a[2] = __float_as_uint(sQ[rb * FSTR + k0 + 4 + lq]);
            a[3] = __float_as_uint(sQ[(rb + 8) * FSTR + k0 + 4 + lq]);
#pragma unroll
            for (int nt = 0; nt < 8; nt++) {
                int nn = nt * 8 + lr;
                unsigned bfx[2];
                bfx[0] = __float_as_uint(cK[nn * FSTR + k0 + lq]);
                bfx[1] = __float_as_uint(cK[nn * FSTR + k0 + 4 + lq]);
                MMA_TF32(S[nt], a, bfx);
            }
        }

        // ---- add BD band, scale, mask ----
        int j0 = jt * 64;
#pragma unroll
        for (int nt = 0; nt < 8; nt++) {
            int jc = j0 + nt * 8 + 2 * lq;
            const float* b0 = bdz + (long long)rowA * 2048 + (1023 - rowA + jc);
            const float* b1 = bdz + (long long)(rowA + 8) * 2048 + (1015 - rowA + jc);
            float s0 = (S[nt][0] + __ldg(b0)) * SCALE_F;
            float s1 = (S[nt][1] + __ldg(b0 + 1)) * SCALE_F;
            float s2 = (S[nt][2] + __ldg(b1)) * SCALE_F;
            float s3 = (S[nt][3] + __ldg(b1 + 1)) * SCALE_F;
            if (sMask[jc] != 0.f)     { s0 = -1e30f; s2 = -1e30f; }
            if (sMask[jc + 1] != 0.f) { s1 = -1e30f; s3 = -1e30f; }
            S[nt][0] = s0; S[nt][1] = s1; S[nt][2] = s2; S[nt][3] = s3;
        }

        // ---- online softmax ----
        float mxA = -3.4e38f, mxB = -3.4e38f;
#pragma unroll
        for (int nt = 0; nt < 8; nt++) {
            mxA = fmaxf(mxA, fmaxf(S[nt][0], S[nt][1]));
            mxB = fmaxf(mxB, fmaxf(S[nt][2], S[nt][3]));
        }
        mxA = fmaxf(mxA, __shfl_xor_sync(0xffffffffu, mxA, 1));
        mxA = fmaxf(mxA, __shfl_xor_sync(0xffffffffu, mxA, 2));
        mxB = fmaxf(mxB, __shfl_xor_sync(0xffffffffu, mxB, 1));
        mxB = fmaxf(mxB, __shfl_xor_sync(0xffffffffu, mxB, 2));
        float nmA = fmaxf(mA, mxA), nmB = fmaxf(mB, mxB);
        float scA = __expf(mA - nmA), scB = __expf(mB - nmB);
        mA = nmA; mB = nmB;
        float smA = 0.f, smB = 0.f;
#pragma unroll
        for (int nt = 0; nt < 8; nt++) {
            int jc = nt * 8 + 2 * lq;
            float p0 = __expf(S[nt][0] - nmA), p1 = __expf(S[nt][1] - nmA);
            float p2 = __expf(S[nt][2] - nmB), p3 = __expf(S[nt][3] - nmB);
            smA += p0 + p1; smB += p2 + p3;
            sP[rb * FSTR + jc] = p0; sP[rb * FSTR + jc + 1] = p1;
            sP[(rb + 8) * FSTR + jc] = p2; sP[(rb + 8) * FSTR + jc + 1] = p3;
        }
        smA += __shfl_xor_sync(0xffffffffu, smA, 1);
        smA += __shfl_xor_sync(0xffffffffu, smA, 2);
        smB += __shfl_xor_sync(0xffffffffu, smB, 1);
        smB += __shfl_xor_sync(0xffffffffu, smB, 2);
        lA = lA * scA + smA;
        lB = lB * scB + smB;
#pragma unroll
        for (int nt = 0; nt < 8; nt++) {
            O[nt][0] *= scA; O[nt][1] *= scA;
            O[nt][2] *= scB; O[nt][3] *= scB;
        }
        __syncthreads();  // sP written by all warps

        // ---- O += P @ V ----
        float* cV = sV + buf * 64 * 64;
#pragma unroll
        for (int kc = 0; kc < 8; kc++) {
            int k0 = kc * 8;
            unsigned a[4];
            a[0] = __float_as_uint(sP[rb * FSTR + k0 + lq]);
            a[1] = __float_as_uint(sP[(rb + 8) * FSTR + k0 + lq]);
            a[2] = __float_as_uint(sP[rb * FSTR + k0 + 4 + lq]);
            a[3] = __float_as_uint(sP[(rb + 8) * FSTR + k0 + 4 + lq]);
#pragma unroll
            for (int nt = 0; nt < 8; nt++) {
                int nn = nt * 8 + lr;
                unsigned bfx[2];
                bfx[0] = __float_as_uint(cV[swzB(k0 + lq, nn)]);
                bfx[1] = __float_as_uint(cV[swzB(k0 + 4 + lq, nn)]);
                MMA_TF32(O[nt], a, bfx);
            }
        }
        __syncthreads();  // everyone done with sP & this K/V buffer

        if (jt + 2 < 16) loadKV(jt + 2, buf);  // refill the buffer just freed
    }

    // ---- finalize: O /= l, store to vec [(i*2+b)][nh*64+d] ----
    float iA = 1.0f / lA, iB = 1.0f / lB;
#pragma unroll
    for (int nt = 0; nt < 8; nt++) {
        int d0 = nt * 8 + 2 * lq;
        long long baseA = (((long long)(rowA * 2 + b)) << 10) + nh * 64 + d0;
        long long baseB = (((long long)((rowA + 8) * 2 + b)) << 10) + nh * 64 + d0;
        vec[baseA] = O[nt][0] * iA; vec[baseA + 1] = O[nt][1] * iA;
        vec[baseB] = O[nt][2] * iB; vec[baseB + 1] = O[nt][3] * iB;
    }
}

// ---------------- residual + LayerNorm ----------------
__global__ void ln_k(const float* __restrict__ w, const float* __restrict__ xb,
                     const float* __restrict__ g, const float* __restrict__ bb,
                     float* __restrict__ out) {
    __shared__ float smr[16];
    int row = blockIdx.x, t = threadIdx.x;
    const float* wr = w + (long long)row * 1024;
    const float* xr = xb + (long long)row * 1024;
    float loc[4], s = 0.f, sq = 0.f;
#pragma unroll
    for (int e = 0; e < 4; e++) {
        float x = wr[e * 256 + t] + xr[e * 256 + t];
        loc[e] = x; s += x; sq += x * x;
    }
#pragma unroll
    for (int o = 16; o; o >>= 1) {
        s += __shfl_xor_sync(0xffffffffu, s, o);
        sq += __shfl_xor_sync(0xffffffffu, sq, o);
    }
    if ((t & 31) == 0) { smr[t >> 5] = s; smr[8 + (t >> 5)] = sq; }
    __syncthreads();
    s = smr[t & 7]; sq = smr[8 + (t & 7)];
#pragma unroll
    for (int o = 4; o; o >>= 1) {
        s += __shfl_xor_sync(0xffffffffu, s, o);
        sq += __shfl_xor_sync(0xffffffffu, sq, o);
    }
    float mu = s * (1.0f / 1024.0f);
    float var = sq * (1.0f / 1024.0f) - mu * mu;
    float rstd = rsqrtf(var + EPS_F);
#pragma unroll
    for (int e = 0; e < 4; e++) {
        int c = e * 256 + t;
        out[(long long)row * 1024 + c] = (loc[e] - mu) * rstd * g[c] + bb[c];
    }
}

// ---------------- launch ----------------
extern "C" void kernel_launch(void* const* d_in, const int* in_sizes, int n_in,
                              void* d_out, int out_size) {
    const float* w    = (const float*)d_in[0];
    const float* r    = (const float*)d_in[1];
    const float* rwb  = (const float*)d_in[2];
    const float* rrb  = (const float*)d_in[3];
    const unsigned char* mask = (const unsigned char*)d_in[4];
    const float* Wqkv = (const float*)d_in[5];
    const float* Wrfw = (const float*)d_in[6];
    const float* Wrbw = (const float*)d_in[7];
    const float* Wo   = (const float*)d_in[8];
    const float* lng  = (const float*)d_in[9];
    const float* lnb  = (const float*)d_in[10];
    float* out = (float*)d_out;

    float *q1, *q2, *kk, *vv, *rk, *bd, *vec, *xb;
    cudaGetSymbolAddress((void**)&q1, g_q1);
    cudaGetSymbolAddress((void**)&q2, g_q2);
    cudaGetSymbolAddress((void**)&kk, g_kk);
    cudaGetSymbolAddress((void**)&vv, g_vv);
    cudaGetSymbolAddress((void**)&rk, g_rk);
    cudaGetSymbolAddress((void**)&bd, g_bd);
    cudaGetSymbolAddress((void**)&vec, g_vec);
    cudaGetSymbolAddress((void**)&xb, g_x);

    // zero pad row 2047 of rk
    zero_k<<<4, 256>>>(rk + 2047 * 1024);

    // QKV GEMM with fused head scatter (+biases)
    gemm_k<0, 2, 0><<<dim3(48, 16, 1), 256>>>(w, Wqkv, q1, 2048, 3072, 1024,
                                              1024, 3072, 0, 0, 0, 0,
                                              rwb, rrb, q2, kk, vv);
    // merged r_fw (bx<16 -> rk, ldc 1024) + r_bw reversed (bx>=16 -> rk+2046*1024, ldc -1024)
    gemm_k<0, 0, 2><<<dim3(32, 8, 1), 256>>>(r, Wrfw, rk, 1024, 1024, 1024,
                                             1024, 1024, 1024, 0, 0, 0,
                                             Wrbw, 0, rk + 2046 * 1024, 0, 0);
    // BD band = Q2 @ rk^T (18 diagonal col-tiles per i-tile)
    gemm_k<1, 0, 1><<<dim3(18, 8, 32), 256>>>(q2, rk, bd, 1024, 2048, 64,
                                              64, 1024, 2048, 65536, 0, 1LL << 21,
                                              0, 0, 0, 0, 0);
    // fused AC + BD + mask + softmax + PV
    int fl_smem = (256 * FSTR + 2 * 64 * FSTR + 2 * 64 * 64 + 1024) * (int)sizeof(float);
    cudaFuncSetAttribute(flash_k, cudaFuncAttributeMaxDynamicSharedMemorySize, fl_smem);
    flash_k<<<dim3(8, 32), 256, fl_smem>>>(q1, kk, vv, bd, mask, vec);
    // attn_out = vec @ W_o
    gemm_k<0, 0, 0><<<dim3(16, 16, 1), 256>>>(vec, Wo, xb, 2048, 1024, 1024,
                                              1024, 1024, 1024, 0, 0, 0,
                                              0, 0, 0, 0, 0);
    // residual + LN
    ln_k<<<2048, 256>>>(w, xb, lng, lnb, out);
}

// round 7
// speedup vs baseline: 3.0867x; 1.0282x over previous
#include <cuda_runtime.h>
#include <math.h>

#define SCALE_F 0.125f
#define EPS_F 1e-5f

// ---------------- scratch (device globals) ----------------
__device__ float g_q1[32 * 1024 * 64];   // q + r_w_bias, [z][i][64]
__device__ float g_q2[32 * 1024 * 64];   // q + r_r_bias
__device__ float g_kk[32 * 1024 * 64];   // k heads
__device__ float g_vv[32 * 1024 * 64];   // v heads
__device__ float g_rk[2048 * 1024];      // r_k padded to 2048 rows (row 2047 zeroed)
__device__ float g_bd[67108864];         // BD [z][1024][2048] (band-only written)
__device__ float g_vec[2048 * 1024];     // attn vec [(i*2+b)][n*64+d]
__device__ float g_x[2048 * 1024];       // vec @ W_o

// ---------------- helpers ----------------
__device__ __forceinline__ void cp16(float* s, const float* g) {
    unsigned a = (unsigned)__cvta_generic_to_shared(s);
    asm volatile("cp.async.cg.shared.global [%0], [%1], 16;\n" ::"r"(a), "l"(g));
}
__device__ __forceinline__ int swzA(int r, int col) {  // 16-float rows
    return r * 16 + (((col >> 2) ^ ((r >> 1) & 3)) << 2) + (col & 3);
}
__device__ __forceinline__ int swzB(int k, int n) {    // 64-float rows
    return k * 64 + (((n >> 2) ^ ((2 * k) & 15)) << 2) + (n & 3);
}
#define MMA_TF32(c, a, b)                                                          \
    asm volatile(                                                                  \
        "mma.sync.aligned.m16n8k8.row.col.f32.tf32.tf32.f32 "                      \
        "{%0,%1,%2,%3},{%4,%5,%6,%7},{%8,%9},{%0,%1,%2,%3};"                       \
        : "+f"(c[0]), "+f"(c[1]), "+f"(c[2]), "+f"(c[3])                           \
        : "r"(a[0]), "r"(a[1]), "r"(a[2]), "r"(a[3]), "r"(b[0]), "r"(b[1]))

// ---------------- tf32 tensor-core GEMM, 128x128 tile ----------------
// C[M][N] = A[M][K] @ B.  BNK=1: B given [N][K] row-major (C = A@B^T).
// EPI: 0 plain store, 2 QKV head scatter.
// BOFF=1 (BD): per-head B offset (z&15)*64 + diagonal band col remap (bx<9).
// BOFF=2 (RK): bx>=8 switches to W_r_bw / reversed store (skips row 1023).
template <int BNK, int EPI, int BOFF>
__global__ __launch_bounds__(256, 1) void gemm_k(
    const float* __restrict__ A, const float* __restrict__ B, float* __restrict__ C,
    int K, int lda, int ldb, int ldc,
    long long strA, long long strB, long long strC,
    const float* __restrict__ bias1, const float* __restrict__ bias2,
    float* __restrict__ o2, float* __restrict__ o3, float* __restrict__ o4) {
    __shared__ float sm[2 * 4096];
    int t = threadIdx.x, lane = t & 31, lq = lane & 3, lr = lane >> 2;
    int z = blockIdx.z;
    A += z * strA;
    if (BOFF == 1) B += (long long)(z & 15) * 64; else B += z * strB;
    C += z * strC;
    int row0 = blockIdx.y * 128;
    int col0;
    if (BOFF == 1) col0 = 896 - row0 + blockIdx.x * 128;
    else if (BOFF == 2) col0 = (blockIdx.x & 7) * 128;
    else col0 = blockIdx.x * 128;
    bool bw = (BOFF == 2) && (blockIdx.x >= 8);
    if (bw) { B = bias1; C = o2; ldc = -1024; }
    int warp = t >> 5, wm = warp >> 1, wn = warp & 1;

    float acc[2][8][4] = {};

    auto load_tile = [&](int kt, int st) {
        float* sA = sm + st * 4096;
        float* sB = sA + 2048;
        int k0 = kt * 16;
#pragma unroll
        for (int e = 0; e < 2; e++) {
            int c = e * 256 + t, r = c >> 2, c4 = c & 3;
            cp16(sA + r * 16 + ((c4 ^ ((r >> 1) & 3)) << 2),
                 A + (long long)(row0 + r) * lda + k0 + (c4 << 2));
        }
        if (BNK) {
#pragma unroll
            for (int e = 0; e < 2; e++) {
                int c = e * 256 + t, r = c >> 2, c4 = c & 3;
                cp16(sB + r * 16 + ((c4 ^ ((r >> 1) & 3)) << 2),
                     B + (long long)(col0 + r) * ldb + k0 + (c4 << 2));
            }
        } else {
#pragma unroll
            for (int e = 0; e < 2; e++) {
                int c = e * 256 + t, kr = c >> 5, n4 = c & 31, p = n4 >> 4, n4p = n4 & 15;
                cp16(sB + p * 1024 + kr * 64 + ((n4p ^ ((2 * kr) & 15)) << 2),
                     B + (long long)(k0 + kr) * ldb + col0 + (n4 << 2));
            }
        }
        asm volatile("cp.async.commit_group;\n");
    };

    load_tile(0, 0);
    int KT = K >> 4;
    for (int kt = 0; kt < KT; kt++) {
        int st = kt & 1;
        if (kt + 1 < KT) {
            load_tile(kt + 1, st ^ 1);
            asm volatile("cp.async.wait_group 1;\n");
        } else {
            asm volatile("cp.async.wait_group 0;\n");
        }
        __syncthreads();
        float* sA = sm + st * 4096;
        float* sB = sA + 2048;
#pragma unroll
        for (int ks = 0; ks < 16; ks += 8) {
            unsigned af[2][4], bf[8][2];
#pragma unroll
            for (int mt = 0; mt < 2; mt++) {
                int r = wm * 32 + mt * 16 + lr;
                af[mt][0] = __float_as_uint(sA[swzA(r, ks + lq)]);
                af[mt][1] = __float_as_uint(sA[swzA(r + 8, ks + lq)]);
                af[mt][2] = __float_as_uint(sA[swzA(r, ks + 4 + lq)]);
                af[mt][3] = __float_as_uint(sA[swzA(r + 8, ks + 4 + lq)]);
            }
#pragma unroll
            for (int nt = 0; nt < 8; nt++) {
                int nn = wn * 64 + nt * 8 + lr;
                if (BNK) {
                    bf[nt][0] = __float_as_uint(sB[swzA(nn, ks + lq)]);
                    bf[nt][1] = __float_as_uint(sB[swzA(nn, ks + 4 + lq)]);
                } else {
                    int p = nn >> 6, np = nn & 63;
                    bf[nt][0] = __float_as_uint(sB[p * 1024 + swzB(ks + lq, np)]);
                    bf[nt][1] = __float_as_uint(sB[p * 1024 + swzB(ks + 4 + lq, np)]);
                }
            }
#pragma unroll
            for (int mt = 0; mt < 2; mt++)
#pragma unroll
                for (int nt = 0; nt < 8; nt++) MMA_TF32(acc[mt][nt], af[mt], bf[nt]);
        }
        __syncthreads();
    }

    // epilogue
#pragma unroll
    for (int mt = 0; mt < 2; mt++)
#pragma unroll
        for (int nt = 0; nt < 8; nt++) {
            int r0 = row0 + wm * 32 + mt * 16 + lr;
            int cb = col0 + wn * 64 + nt * 8 + 2 * lq;
#pragma unroll
            for (int e = 0; e < 4; e++) {
                int rr = r0 + (e >> 1) * 8;
                int cc = cb + (e & 1);
                float v = acc[mt][nt][e];
                if (EPI == 0) {
                    if (BOFF == 2 && bw && rr == 1023) continue;  // fw owns rk row 1023
                    C[(long long)rr * (long long)ldc + cc] = v;
                } else {
                    int i = rr >> 1, bb = rr & 1;
                    int sec = cc >> 10, c1 = cc & 1023, n = c1 >> 6, d = c1 & 63;
                    long long idx = (((long long)(bb * 16 + n)) << 16) + (i << 6) + d;
                    if (sec == 0) {
                        C[idx] = v + bias1[c1];   // q1
                        o2[idx] = v + bias2[c1];  // q2
                    } else if (sec == 1) {
                        o3[idx] = v;              // k
                    } else {
                        o4[idx] = v;              // v
                    }
                }
            }
        }
}

// ---------------- zero pad row of rk ----------------
__global__ void zero_k(float* p) { p[blockIdx.x * 256 + threadIdx.x] = 0.0f; }

// ---------------- flash: S = Q1·K^T + BD_band, mask, online softmax, P·V ----------------
// grid (8 i-tiles, 32 z), 256 threads (8 warps), K/V triple-buffered.
#define FSTR 68
__global__ __launch_bounds__(256) void flash_k(
    const float* __restrict__ q1, const float* __restrict__ kk,
    const float* __restrict__ vv, const float* __restrict__ bd,
    const unsigned char* __restrict__ mask, float* __restrict__ vec) {
    extern __shared__ float fs[];
    float* sQ = fs;                       // 128 x 68
    float* sP = sQ + 128 * FSTR;          // 128 x 68 (per-warp-private rows)
    float* sK = sP + 128 * FSTR;          // 3 x 64 x 68
    float* sV = sK + 3 * 64 * FSTR;       // 3 x 64 x 64 (swzB)
    float* sMask = sV + 3 * 64 * 64;      // 1024 flags

    int t = threadIdx.x, lane = t & 31, warp = t >> 5;
    int lq = lane & 3, lr = lane >> 2;
    int i0 = blockIdx.x * 128, z = blockIdx.y, b = z >> 4, nh = z & 15;
    const float* Qz = q1 + ((long long)z << 16);
    const float* Kz = kk + ((long long)z << 16);
    const float* Vz = vv + ((long long)z << 16);
    const float* bdz = bd + ((long long)z << 21);

    for (int e = t; e < 1024; e += 256) sMask[e] = mask[e * 2 + b] ? 1.0f : 0.0f;

#pragma unroll
    for (int e = 0; e < 8; e++) {
        int idx = e * 256 + t, rr = idx >> 4, c4 = idx & 15;
        cp16(sQ + rr * FSTR + c4 * 4, Qz + (long long)(i0 + rr) * 64 + c4 * 4);
    }
    auto loadKV = [&](int jt, int bufi) {
        float* dK = sK + bufi * 64 * FSTR;
        float* dV = sV + bufi * 64 * 64;
        int j0 = jt * 64;
#pragma unroll
        for (int e = 0; e < 4; e++) {
            int idx = e * 256 + t, rr = idx >> 4, c4 = idx & 15;
            cp16(dK + rr * FSTR + c4 * 4, Kz + (long long)(j0 + rr) * 64 + c4 * 4);
            cp16(dV + rr * 64 + (((c4 ^ ((2 * rr) & 15))) << 2),
                 Vz + (long long)(j0 + rr) * 64 + c4 * 4);
        }
        asm volatile("cp.async.commit_group;\n");
    };
    loadKV(0, 0);  // group 0 (with Q)
    loadKV(1, 1);  // group 1

    float mA = -3.4e38f, mB = -3.4e38f, lA = 0.f, lB = 0.f;
    float O[8][4] = {};
    int rb = warp * 16 + lr;
    int rowA = i0 + rb;

    for (int jt = 0; jt < 16; jt++) {
        int buf = jt % 3;
        if (jt == 15) asm volatile("cp.async.wait_group 0;\n");
        else          asm volatile("cp.async.wait_group 1;\n");
        __syncthreads();

        // ---- S = Q1 @ K^T ----
        float* cK = sK + buf * 64 * FSTR;
        float S[8][4] = {};
#pragma unroll
        for (int kc = 0; kc < 8; kc++) {
            int k0 = kc * 8;
            unsigned a[4];
            a[0] = __float_as_uint(sQ[rb * FSTR + k0 + lq]);
            a[1] = __float_as_uint(sQ[(rb + 8) * FSTR + k0 + lq]);
            a[2] = __float_as_uint(sQ[rb * FSTR + k0 + 4 + lq]);
            a[3] = __float_as_uint(sQ[(rb + 8) * FSTR + k0 + 4 + lq]);
#pragma unroll
            for (int nt = 0; nt < 8; nt++) {
                int nn = nt * 8 + lr;
                unsigned bfx[2];
                bfx[0] = __float_as_uint(cK[nn * FSTR + k0 + lq]);
                bfx[1] = __float_as_uint(cK[nn * FSTR + k0 + 4 + lq]);
                MMA_TF32(S[nt], a, bfx);
            }
        }

        // ---- add BD band, scale, mask ----
        int j0 = jt * 64;
#pragma unroll
        for (int nt = 0; nt < 8; nt++) {
            int jc = j0 + nt * 8 + 2 * lq;
            const float* b0 = bdz + (long long)rowA * 2048 + (1023 - rowA + jc);
            const float* b1 = bdz + (long long)(rowA + 8) * 2048 + (1015 - rowA + jc);
            float s0 = (S[nt][0] + __ldg(b0)) * SCALE_F;
            float s1 = (S[nt][1] + __ldg(b0 + 1)) * SCALE_F;
            float s2 = (S[nt][2] + __ldg(b1)) * SCALE_F;
            float s3 = (S[nt][3] + __ldg(b1 + 1)) * SCALE_F;
            if (sMask[jc] != 0.f)     { s0 = -1e30f; s2 = -1e30f; }
            if (sMask[jc + 1] != 0.f) { s1 = -1e30f; s3 = -1e30f; }
            S[nt][0] = s0; S[nt][1] = s1; S[nt][2] = s2; S[nt][3] = s3;
        }

        // ---- online softmax ----
        float mxA = -3.4e38f, mxB = -3.4e38f;
#pragma unroll
        for (int nt = 0; nt < 8; nt++) {
            mxA = fmaxf(mxA, fmaxf(S[nt][0], S[nt][1]));
            mxB = fmaxf(mxB, fmaxf(S[nt][2], S[nt][3]));
        }
        mxA = fmaxf(mxA, __shfl_xor_sync(0xffffffffu, mxA, 1));
        mxA = fmaxf(mxA, __shfl_xor_sync(0xffffffffu, mxA, 2));
        mxB = fmaxf(mxB, __shfl_xor_sync(0xffffffffu, mxB, 1));
        mxB = fmaxf(mxB, __shfl_xor_sync(0xffffffffu, mxB, 2));
        float nmA = fmaxf(mA, mxA), nmB = fmaxf(mB, mxB);
        float scA = __expf(mA - nmA), scB = __expf(mB - nmB);
        mA = nmA; mB = nmB;
        float smA = 0.f, smB = 0.f;
#pragma unroll
        for (int nt = 0; nt < 8; nt++) {
            int jc = nt * 8 + 2 * lq;
            float p0 = __expf(S[nt][0] - nmA), p1 = __expf(S[nt][1] - nmA);
            float p2 = __expf(S[nt][2] - nmB), p3 = __expf(S[nt][3] - nmB);
            smA += p0 + p1; smB += p2 + p3;
            sP[rb * FSTR + jc] = p0; sP[rb * FSTR + jc + 1] = p1;
            sP[(rb + 8) * FSTR + jc] = p2; sP[(rb + 8) * FSTR + jc + 1] = p3;
        }
        smA += __shfl_xor_sync(0xffffffffu, smA, 1);
        smA += __shfl_xor_sync(0xffffffffu, smA, 2);
        smB += __shfl_xor_sync(0xffffffffu, smB, 1);
        smB += __shfl_xor_sync(0xffffffffu, smB, 2);
        lA = lA * scA + smA;
        lB = lB * scB + smB;
#pragma unroll
        for (int nt = 0; nt < 8; nt++) {
            O[nt][0] *= scA; O[nt][1] *= scA;
            O[nt][2] *= scB; O[nt][3] *= scB;
        }
        __syncwarp();  // sP rows are warp-private; cross-lane visibility only

        // ---- O += P @ V ----
        float* cV = sV + buf * 64 * 64;
#pragma unroll
        for (int kc = 0; kc < 8; kc++) {
            int k0 = kc * 8;
            unsigned a[4];
            a[0] = __float_as_uint(sP[rb * FSTR + k0 + lq]);
            a[1] = __float_as_uint(sP[(rb + 8) * FSTR + k0 + lq]);
            a[2] = __float_as_uint(sP[rb * FSTR + k0 + 4 + lq]);
            a[3] = __float_as_uint(sP[(rb + 8) * FSTR + k0 + 4 + lq]);
#pragma unroll
            for (int nt = 0; nt < 8; nt++) {
                int nn = nt * 8 + lr;
                unsigned bfx[2];
                bfx[0] = __float_as_uint(cV[swzB(k0 + lq, nn)]);
                bfx[1] = __float_as_uint(cV[swzB(k0 + 4 + lq, nn)]);
                MMA_TF32(O[nt], a, bfx);
            }
        }

        if (jt + 2 < 16) loadKV(jt + 2, (jt + 2) % 3);
    }

    float iA = 1.0f / lA, iB = 1.0f / lB;
#pragma unroll
    for (int nt = 0; nt < 8; nt++) {
        int d0 = nt * 8 + 2 * lq;
        long long baseA = (((long long)(rowA * 2 + b)) << 10) + nh * 64 + d0;
        long long baseB = (((long long)((rowA + 8) * 2 + b)) << 10) + nh * 64 + d0;
        vec[baseA] = O[nt][0] * iA; vec[baseA + 1] = O[nt][1] * iA;
        vec[baseB] = O[nt][2] * iB; vec[baseB + 1] = O[nt][3] * iB;
    }
}

// ---------------- residual + LayerNorm ----------------
__global__ void ln_k(const float* __restrict__ w, const float* __restrict__ xb,
                     const float* __restrict__ g, const float* __restrict__ bb,
                     float* __restrict__ out) {
    __shared__ float smr[16];
    int row = blockIdx.x, t = threadIdx.x;
    const float* wr = w + (long long)row * 1024;
    const float* xr = xb + (long long)row * 1024;
    float loc[4], s = 0.f, sq = 0.f;
#pragma unroll
    for (int e = 0; e < 4; e++) {
        float x = wr[e * 256 + t] + xr[e * 256 + t];
        loc[e] = x; s += x; sq += x * x;
    }
#pragma unroll
    for (int o = 16; o; o >>= 1) {
        s += __shfl_xor_sync(0xffffffffu, s, o);
        sq += __shfl_xor_sync(0xffffffffu, sq, o);
    }
    if ((t & 31) == 0) { smr[t >> 5] = s; smr[8 + (t >> 5)] = sq; }
    __syncthreads();
    s = smr[t & 7]; sq = smr[8 + (t & 7)];
#pragma unroll
    for (int o = 4; o; o >>= 1) {
        s += __shfl_xor_sync(0xffffffffu, s, o);
        sq += __shfl_xor_sync(0xffffffffu, sq, o);
    }
    float mu = s * (1.0f / 1024.0f);
    float var = sq * (1.0f / 1024.0f) - mu * mu;
    float rstd = rsqrtf(var + EPS_F);
#pragma unroll
    for (int e = 0; e < 4; e++) {
        int c = e * 256 + t;
        out[(long long)row * 1024 + c] = (loc[e] - mu) * rstd * g[c] + bb[c];
    }
}

// ---------------- launch ----------------
extern "C" void kernel_launch(void* const* d_in, const int* in_sizes, int n_in,
                              void* d_out, int out_size) {
    const float* w    = (const float*)d_in[0];
    const float* r    = (const float*)d_in[1];
    const float* rwb  = (const float*)d_in[2];
    const float* rrb  = (const float*)d_in[3];
    const unsigned char* mask = (const unsigned char*)d_in[4];
    const float* Wqkv = (const float*)d_in[5];
    const float* Wrfw = (const float*)d_in[6];
    const float* Wrbw = (const float*)d_in[7];
    const float* Wo   = (const float*)d_in[8];
    const float* lng  = (const float*)d_in[9];
    const float* lnb  = (const float*)d_in[10];
    float* out = (float*)d_out;

    float *q1, *q2, *kk, *vv, *rk, *bd, *vec, *xb;
    cudaGetSymbolAddress((void**)&q1, g_q1);
    cudaGetSymbolAddress((void**)&q2, g_q2);
    cudaGetSymbolAddress((void**)&kk, g_kk);
    cudaGetSymbolAddress((void**)&vv, g_vv);
    cudaGetSymbolAddress((void**)&rk, g_rk);
    cudaGetSymbolAddress((void**)&bd, g_bd);
    cudaGetSymbolAddress((void**)&vec, g_vec);
    cudaGetSymbolAddress((void**)&xb, g_x);

    // zero pad row 2047 of rk
    zero_k<<<4, 256>>>(rk + 2047 * 1024);

    // QKV GEMM with fused head scatter (+biases)
    gemm_k<0, 2, 0><<<dim3(24, 16, 1), 256>>>(w, Wqkv, q1, 1024,
                                              1024, 3072, 0, 0, 0, 0,
                                              rwb, rrb, q2, kk, vv);
    // merged r_fw (bx<8 -> rk) + r_bw reversed (bx>=8 -> rk+2046*1024, ldc -1024, skip row 1023)
    gemm_k<0, 0, 2><<<dim3(16, 8, 1), 256>>>(r, Wrfw, rk, 1024,
                                             1024, 1024, 1024, 0, 0, 0,
                                             Wrbw, 0, rk + 2046 * 1024, 0, 0);
    // BD band = Q2 @ rk^T (9 diagonal 128-col tiles per i-tile)
    gemm_k<1, 0, 1><<<dim3(9, 8, 32), 256>>>(q2, rk, bd, 64,
                                             64, 1024, 2048, 65536, 0, 1LL << 21,
                                             0, 0, 0, 0, 0);
    // fused AC + BD + mask + softmax + PV
    int fl_smem = (256 * FSTR + 3 * 64 * FSTR + 3 * 64 * 64 + 1024) * (int)sizeof(float);
    cudaFuncSetAttribute(flash_k, cudaFuncAttributeMaxDynamicSharedMemorySize, fl_smem);
    flash_k<<<dim3(8, 32), 256, fl_smem>>>(q1, kk, vv, bd, mask, vec);
    // attn_out = vec @ W_o
    gemm_k<0, 0, 0><<<dim3(8, 16, 1), 256>>>(vec, Wo, xb, 1024,
                                             1024, 1024, 1024, 0, 0, 0,
                                             0, 0, 0, 0, 0);
    // residual + LN
    ln_k<<<2048, 256>>>(w, xb, lng, lnb, out);
}

// round 8
// speedup vs baseline: 3.9196x; 1.2699x over previous
#include <cuda_runtime.h>
#include <cuda_bf16.h>
#include <math.h>

#define SCALE_F 0.125f
#define EPS_F 1e-5f

// ---------------- scratch (device globals) ----------------
__device__ unsigned g_q1u[32 * 1024 * 32];  // q + r_w_bias, bf16x2 [z][i][32]
__device__ unsigned g_q2u[32 * 1024 * 32];  // q + r_r_bias, bf16x2
__device__ unsigned g_kku[32 * 1024 * 32];  // k heads, bf16x2
__device__ float    g_vv[32 * 1024 * 64];   // v heads fp32 [z][i][64]
__device__ unsigned g_rku[2048 * 512];      // r_k bf16x2 [jr][512] (row 2047 zeroed)
__device__ float    g_bd[67108864];         // BD [z][1024][2048] fp32 (band only)
__device__ float    g_vec[2048 * 1024];     // attn vec [(i*2+b)][n*64+d]
__device__ float    g_x[2048 * 1024];       // vec @ W_o

// ---------------- helpers ----------------
__device__ __forceinline__ void cp16(void* s, const void* g) {
    unsigned a = (unsigned)__cvta_generic_to_shared(s);
    asm volatile("cp.async.cg.shared.global [%0], [%1], 16;\n" ::"r"(a), "l"(g));
}
__device__ __forceinline__ unsigned packbf(float lo, float hi) {
    unsigned u;
    asm("cvt.rn.bf16x2.f32 %0, %1, %2;" : "=r"(u) : "f"(hi), "f"(lo));
    return u;
}
__device__ __forceinline__ int swzA(int r, int col) {  // 16-float rows (tf32 A)
    return r * 16 + (((col >> 2) ^ ((r >> 1) & 3)) << 2) + (col & 3);
}
__device__ __forceinline__ int swzB(int k, int n) {    // 64-float rows (fp32 V/B)
    return k * 64 + (((n >> 2) ^ ((2 * k) & 15)) << 2) + (n & 3);
}
// bf16x2 rows of 32 u32 (=64 bf16), XOR swizzle: conflict-free frag access
__device__ __forceinline__ int adru(int r, int c) {
    return r * 32 + (((c >> 2) ^ (r & 7)) << 2) + (c & 3);
}
#define MMA_TF32(c, a, b)                                                          \
    asm volatile(                                                                  \
        "mma.sync.aligned.m16n8k8.row.col.f32.tf32.tf32.f32 "                      \
        "{%0,%1,%2,%3},{%4,%5,%6,%7},{%8,%9},{%0,%1,%2,%3};"                       \
        : "+f"(c[0]), "+f"(c[1]), "+f"(c[2]), "+f"(c[3])                           \
        : "r"(a[0]), "r"(a[1]), "r"(a[2]), "r"(a[3]), "r"(b[0]), "r"(b[1]))
#define MMA_BF16(c, a, b)                                                          \
    asm volatile(                                                                  \
        "mma.sync.aligned.m16n8k16.row.col.f32.bf16.bf16.f32 "                     \
        "{%0,%1,%2,%3},{%4,%5,%6,%7},{%8,%9},{%0,%1,%2,%3};"                       \
        : "+f"(c[0]), "+f"(c[1]), "+f"(c[2]), "+f"(c[3])                           \
        : "r"(a[0]), "r"(a[1]), "r"(a[2]), "r"(a[3]), "r"(b[0]), "r"(b[1]))

// ---------------- tf32 GEMM 128x128 (A fp32, B fp32 [K][N]) ----------------
// EPI 0: fp32 store C.  EPI 2: QKV scatter (q1/q2/kk bf16x2 + vv fp32).
// EPI 3: rk bf16x2; bx>=8 -> B2 (W_r_bw), reversed dest u2, skip row 1023.
template <int EPI>
__global__ __launch_bounds__(256, 1) void gemm_k(
    const float* __restrict__ A, const float* __restrict__ B, float* __restrict__ C,
    int K, int lda, int ldb, int ldc,
    const float* __restrict__ B2,
    const float* __restrict__ bias1, const float* __restrict__ bias2,
    unsigned* __restrict__ u1, unsigned* __restrict__ u2, unsigned* __restrict__ u3,
    float* __restrict__ f4) {
    __shared__ float sm[2 * 4096];
    int t = threadIdx.x, lane = t & 31, lq = lane & 3, lr = lane >> 2;
    int row0 = blockIdx.y * 128;
    int col0 = (EPI == 3) ? (blockIdx.x & 7) * 128 : blockIdx.x * 128;
    bool bw = (EPI == 3) && (blockIdx.x >= 8);
    if (bw) B = B2;
    int warp = t >> 5, wm = warp >> 1, wn = warp & 1;

    float acc[2][8][4] = {};

    auto load_tile = [&](int kt, int st) {
        float* sA = sm + st * 4096;
        float* sB = sA + 2048;
        int k0 = kt * 16;
#pragma unroll
        for (int e = 0; e < 2; e++) {
            int c = e * 256 + t, r = c >> 2, c4 = c & 3;
            cp16(sA + r * 16 + ((c4 ^ ((r >> 1) & 3)) << 2),
                 A + (long long)(row0 + r) * lda + k0 + (c4 << 2));
        }
#pragma unroll
        for (int e = 0; e < 2; e++) {
            int c = e * 256 + t, kr = c >> 5, n4 = c & 31, p = n4 >> 4, n4p = n4 & 15;
            cp16(sB + p * 1024 + kr * 64 + ((n4p ^ ((2 * kr) & 15)) << 2),
                 B + (long long)(k0 + kr) * ldb + col0 + (n4 << 2));
        }
        asm volatile("cp.async.commit_group;\n");
    };

    load_tile(0, 0);
    int KT = K >> 4;
    for (int kt = 0; kt < KT; kt++) {
        int st = kt & 1;
        if (kt + 1 < KT) {
            load_tile(kt + 1, st ^ 1);
            asm volatile("cp.async.wait_group 1;\n");
        } else {
            asm volatile("cp.async.wait_group 0;\n");
        }
        __syncthreads();
        float* sA = sm + st * 4096;
        float* sB = sA + 2048;
#pragma unroll
        for (int ks = 0; ks < 16; ks += 8) {
            unsigned af[2][4], bf[8][2];
#pragma unroll
            for (int mt = 0; mt < 2; mt++) {
                int r = wm * 32 + mt * 16 + lr;
                af[mt][0] = __float_as_uint(sA[swzA(r, ks + lq)]);
                af[mt][1] = __float_as_uint(sA[swzA(r + 8, ks + lq)]);
                af[mt][2] = __float_as_uint(sA[swzA(r, ks + 4 + lq)]);
                af[mt][3] = __float_as_uint(sA[swzA(r + 8, ks + 4 + lq)]);
            }
#pragma unroll
            for (int nt = 0; nt < 8; nt++) {
                int nn = wn * 64 + nt * 8 + lr;
                int p = nn >> 6, np = nn & 63;
                bf[nt][0] = __float_as_uint(sB[p * 1024 + swzB(ks + lq, np)]);
                bf[nt][1] = __float_as_uint(sB[p * 1024 + swzB(ks + 4 + lq, np)]);
            }
#pragma unroll
            for (int mt = 0; mt < 2; mt++)
#pragma unroll
                for (int nt = 0; nt < 8; nt++) MMA_TF32(acc[mt][nt], af[mt], bf[nt]);
        }
        __syncthreads();
    }

    // epilogue (pair-based: cols cb, cb+1 adjacent)
#pragma unroll
    for (int mt = 0; mt < 2; mt++)
#pragma unroll
        for (int nt = 0; nt < 8; nt++) {
            int r0 = row0 + wm * 32 + mt * 16 + lr;
            int cb = col0 + wn * 64 + nt * 8 + 2 * lq;
#pragma unroll
            for (int pe = 0; pe < 2; pe++) {
                int rr = r0 + pe * 8;
                float v0 = acc[mt][nt][pe * 2], v1 = acc[mt][nt][pe * 2 + 1];
                if (EPI == 0) {
                    C[(long long)rr * ldc + cb] = v0;
                    C[(long long)rr * ldc + cb + 1] = v1;
                } else if (EPI == 3) {
                    if (bw) {
                        if (rr == 1023) continue;  // fw owns rk row 1023
                        u2[(long long)rr * (-512) + (cb >> 1)] = packbf(v0, v1);
                    } else {
                        u1[(long long)rr * 512 + (cb >> 1)] = packbf(v0, v1);
                    }
                } else {  // EPI == 2: QKV scatter
                    int i = rr >> 1, bb = rr & 1;
                    int sec = cb >> 10, c1 = cb & 1023, n = c1 >> 6, d = c1 & 63;
                    int z = bb * 16 + n;
                    if (sec == 0) {
                        long long idx = ((long long)z << 15) + (i << 5) + (d >> 1);
                        u1[idx] = packbf(v0 + bias1[c1], v1 + bias1[c1 + 1]);
                        u2[idx] = packbf(v0 + bias2[c1], v1 + bias2[c1 + 1]);
                    } else if (sec == 1) {
                        u3[((long long)z << 15) + (i << 5) + (d >> 1)] = packbf(v0, v1);
                    } else {
                        long long idx = ((long long)z << 16) + (i << 6) + d;
                        f4[idx] = v0; f4[idx + 1] = v1;
                    }
                }
            }
        }
}

// ---------------- zero pad row (u32) ----------------
__global__ void zero_u(unsigned* p) { p[blockIdx.x * 256 + threadIdx.x] = 0u; }

// ---------------- bf16 BD band GEMM: bd[z][i][jr] = q2_z[i] . rk[jr] ----------------
// grid (9, 8, 32), 256 threads, single smem stage (K=64 -> 4 MMA k-steps).
__global__ __launch_bounds__(256, 2) void bd_k(
    const unsigned* __restrict__ q2, const unsigned* __restrict__ rk,
    float* __restrict__ bd) {
    __shared__ unsigned su[2 * 4096];
    unsigned* sA = su;
    unsigned* sB = su + 4096;
    int t = threadIdx.x, lane = t & 31, lq = lane & 3, lr = lane >> 2;
    int z = blockIdx.z;
    const unsigned* Az = q2 + ((long long)z << 15);
    const unsigned* Bz = rk + (long long)(z & 15) * 32;
    float* Cz = bd + ((long long)z << 21);
    int row0 = blockIdx.y * 128;
    int col0 = 896 - row0 + blockIdx.x * 128;
    int warp = t >> 5, wm = warp >> 1, wn = warp & 1;

    // load A tile 128x32 u32, B tile 128x32 u32 (head slice of rk rows)
#pragma unroll
    for (int e = 0; e < 4; e++) {
        int c = e * 256 + t, r = c >> 3, c4 = c & 7;
        cp16(sA + r * 32 + ((c4 ^ (r & 7)) << 2), Az + (long long)(row0 + r) * 32 + c4 * 4);
        cp16(sB + r * 32 + ((c4 ^ (r & 7)) << 2), Bz + (long long)(col0 + r) * 512 + c4 * 4);
    }
    asm volatile("cp.async.commit_group;\ncp.async.wait_group 0;\n");
    __syncthreads();

    float acc[2][8][4] = {};
#pragma unroll
    for (int s = 0; s < 4; s++) {
        unsigned af[2][4], bf[8][2];
#pragma unroll
        for (int mt = 0; mt < 2; mt++) {
            int r = wm * 32 + mt * 16 + lr;
            af[mt][0] = sA[adru(r, s * 8 + lq)];
            af[mt][1] = sA[adru(r + 8, s * 8 + lq)];
            af[mt][2] = sA[adru(r, s * 8 + 4 + lq)];
            af[mt][3] = sA[adru(r + 8, s * 8 + 4 + lq)];
        }
#pragma unroll
        for (int nt = 0; nt < 8; nt++) {
            int nn = wn * 64 + nt * 8 + lr;
            bf[nt][0] = sB[adru(nn, s * 8 + lq)];
            bf[nt][1] = sB[adru(nn, s * 8 + 4 + lq)];
        }
#pragma unroll
        for (int mt = 0; mt < 2; mt++)
#pragma unroll
            for (int nt = 0; nt < 8; nt++) MMA_BF16(acc[mt][nt], af[mt], bf[nt]);
    }

#pragma unroll
    for (int mt = 0; mt < 2; mt++)
#pragma unroll
        for (int nt = 0; nt < 8; nt++) {
            int r0 = row0 + wm * 32 + mt * 16 + lr;
            int cb = col0 + wn * 64 + nt * 8 + 2 * lq;
#pragma unroll
            for (int pe = 0; pe < 2; pe++) {
                int rr = r0 + pe * 8;
                Cz[(long long)rr * 2048 + cb] = acc[mt][nt][pe * 2];
                Cz[(long long)rr * 2048 + cb + 1] = acc[mt][nt][pe * 2 + 1];
            }
        }
}

// ---------------- flash (bf16): S = Q1·K^T + BD_band, mask, online softmax, P·V ----------------
__global__ __launch_bounds__(256) void flash_k(
    const unsigned* __restrict__ q1, const unsigned* __restrict__ kk,
    const float* __restrict__ vv, const float* __restrict__ bd,
    const unsigned char* __restrict__ mask, float* __restrict__ vec) {
    extern __shared__ unsigned fsu[];
    unsigned* sQ = fsu;                   // 128 x 32 u32
    unsigned* sP = sQ + 4096;             // 128 x 32 u32
    unsigned* sK = sP + 4096;             // 3 x 64 x 32 u32
    float* sV = (float*)(sK + 3 * 2048);  // 3 x 64 x 64 fp32 (swzB)
    float* sMask = sV + 3 * 4096;         // 1024 flags

    int t = threadIdx.x, lane = t & 31, warp = t >> 5;
    int lq = lane & 3, lr = lane >> 2;
    int i0 = blockIdx.x * 128, z = blockIdx.y, b = z >> 4, nh = z & 15;
    const unsigned* Qz = q1 + ((long long)z << 15);
    const unsigned* Kz = kk + ((long long)z << 15);
    const float* Vz = vv + ((long long)z << 16);
    const float* bdz = bd + ((long long)z << 21);

    for (int e = t; e < 1024; e += 256) sMask[e] = mask[e * 2 + b] ? 1.0f : 0.0f;

    // Q tile: 128x32 u32
#pragma unroll
    for (int e = 0; e < 4; e++) {
        int c = e * 256 + t, r = c >> 3, c4 = c & 7;
        cp16(sQ + r * 32 + ((c4 ^ (r & 7)) << 2), Qz + (long long)(i0 + r) * 32 + c4 * 4);
    }
    auto loadKV = [&](int jt, int bufi) {
        unsigned* dK = sK + bufi * 2048;
        float* dV = sV + bufi * 4096;
        int j0 = jt * 64;
#pragma unroll
        for (int e = 0; e < 2; e++) {
            int c = e * 256 + t, r = c >> 3, c4 = c & 7;
            cp16(dK + r * 32 + ((c4 ^ (r & 7)) << 2), Kz + (long long)(j0 + r) * 32 + c4 * 4);
        }
#pragma unroll
        for (int e = 0; e < 4; e++) {
            int c = e * 256 + t, rr = c >> 4, c4 = c & 15;
            cp16(dV + rr * 64 + ((c4 ^ ((2 * rr) & 15)) << 2),
                 Vz + (long long)(j0 + rr) * 64 + c4 * 4);
        }
        asm volatile("cp.async.commit_group;\n");
    };
    loadKV(0, 0);  // group 0 (with Q)
    loadKV(1, 1);  // group 1

    float mA = -3.4e38f, mB = -3.4e38f, lA = 0.f, lB = 0.f;
    float O[8][4] = {};
    int rb = warp * 16 + lr;
    int rowA = i0 + rb;

    for (int jt = 0; jt < 16; jt++) {
        int buf = jt % 3;
        if (jt == 15) asm volatile("cp.async.wait_group 0;\n");
        else          asm volatile("cp.async.wait_group 1;\n");
        __syncthreads();

        // ---- S = Q1 @ K^T (bf16, k16) ----
        unsigned* cK = sK + buf * 2048;
        float S[8][4] = {};
#pragma unroll
        for (int s = 0; s < 4; s++) {
            unsigned a[4];
            a[0] = sQ[adru(rb, s * 8 + lq)];
            a[1] = sQ[adru(rb + 8, s * 8 + lq)];
            a[2] = sQ[adru(rb, s * 8 + 4 + lq)];
            a[3] = sQ[adru(rb + 8, s * 8 + 4 + lq)];
#pragma unroll
            for (int nt = 0; nt < 8; nt++) {
                int nn = nt * 8 + lr;
                unsigned bfx[2];
                bfx[0] = cK[adru(nn, s * 8 + lq)];
                bfx[1] = cK[adru(nn, s * 8 + 4 + lq)];
                MMA_BF16(S[nt], a, bfx);
            }
        }

        // ---- add BD band, scale, mask ----
        int j0 = jt * 64;
#pragma unroll
        for (int nt = 0; nt < 8; nt++) {
            int jc = j0 + nt * 8 + 2 * lq;
            const float* b0 = bdz + (long long)rowA * 2048 + (1023 - rowA + jc);
            const float* b1 = bdz + (long long)(rowA + 8) * 2048 + (1015 - rowA + jc);
            float s0 = (S[nt][0] + __ldg(b0)) * SCALE_F;
            float s1 = (S[nt][1] + __ldg(b0 + 1)) * SCALE_F;
            float s2 = (S[nt][2] + __ldg(b1)) * SCALE_F;
            float s3 = (S[nt][3] + __ldg(b1 + 1)) * SCALE_F;
            if (sMask[jc] != 0.f)     { s0 = -1e30f; s2 = -1e30f; }
            if (sMask[jc + 1] != 0.f) { s1 = -1e30f; s3 = -1e30f; }
            S[nt][0] = s0; S[nt][1] = s1; S[nt][2] = s2; S[nt][3] = s3;
        }

        // ---- online softmax ----
        float mxA = -3.4e38f, mxB = -3.4e38f;
#pragma unroll
        for (int nt = 0; nt < 8; nt++) {
            mxA = fmaxf(mxA, fmaxf(S[nt][0], S[nt][1]));
            mxB = fmaxf(mxB, fmaxf(S[nt][2], S[nt][3]));
        }
        mxA = fmaxf(mxA, __shfl_xor_sync(0xffffffffu, mxA, 1));
        mxA = fmaxf(mxA, __shfl_xor_sync(0xffffffffu, mxA, 2));
        mxB = fmaxf(mxB, __shfl_xor_sync(0xffffffffu, mxB, 1));
        mxB = fmaxf(mxB, __shfl_xor_sync(0xffffffffu, mxB, 2));
        float nmA = fmaxf(mA, mxA), nmB = fmaxf(mB, mxB);
        float scA = __expf(mA - nmA), scB = __expf(mB - nmB);
        mA = nmA; mB = nmB;
        float smA = 0.f, smB = 0.f;
#pragma unroll
        for (int nt = 0; nt < 8; nt++) {
            float p0 = __expf(S[nt][0] - nmA), p1 = __expf(S[nt][1] - nmA);
            float p2 = __expf(S[nt][2] - nmB), p3 = __expf(S[nt][3] - nmB);
            smA += p0 + p1; smB += p2 + p3;
            sP[adru(rb, nt * 4 + lq)] = packbf(p0, p1);
            sP[adru(rb + 8, nt * 4 + lq)] = packbf(p2, p3);
        }
        smA += __shfl_xor_sync(0xffffffffu, smA, 1);
        smA += __shfl_xor_sync(0xffffffffu, smA, 2);
        smB += __shfl_xor_sync(0xffffffffu, smB, 1);
        smB += __shfl_xor_sync(0xffffffffu, smB, 2);
        lA = lA * scA + smA;
        lB = lB * scB + smB;
#pragma unroll
        for (int nt = 0; nt < 8; nt++) {
            O[nt][0] *= scA; O[nt][1] *= scA;
            O[nt][2] *= scB; O[nt][3] *= scB;
        }
        __syncwarp();  // sP rows are warp-private

        // ---- O += P @ V (bf16 A from sP, B packed from fp32 V) ----
        float* cV = sV + buf * 4096;
#pragma unroll
        for (int s = 0; s < 4; s++) {
            int k16 = s * 16;
            unsigned a[4];
            a[0] = sP[adru(rb, s * 8 + lq)];
            a[1] = sP[adru(rb + 8, s * 8 + lq)];
            a[2] = sP[adru(rb, s * 8 + 4 + lq)];
            a[3] = sP[adru(rb + 8, s * 8 + 4 + lq)];
#pragma unroll
            for (int nt = 0; nt < 8; nt++) {
                int nn = nt * 8 + lr;
                unsigned bfx[2];
                bfx[0] = packbf(cV[swzB(k16 + 2 * lq, nn)], cV[swzB(k16 + 2 * lq + 1, nn)]);
                bfx[1] = packbf(cV[swzB(k16 + 2 * lq + 8, nn)], cV[swzB(k16 + 2 * lq + 9, nn)]);
                MMA_BF16(O[nt], a, bfx);
            }
        }

        if (jt + 2 < 16) loadKV(jt + 2, (jt + 2) % 3);
    }

    float iA = 1.0f / lA, iB = 1.0f / lB;
#pragma unroll
    for (int nt = 0; nt < 8; nt++) {
        int d0 = nt * 8 + 2 * lq;
        long long baseA = (((long long)(rowA * 2 + b)) << 10) + nh * 64 + d0;
        long long baseB = (((long long)((rowA + 8) * 2 + b)) << 10) + nh * 64 + d0;
        vec[baseA] = O[nt][0] * iA; vec[baseA + 1] = O[nt][1] * iA;
        vec[baseB] = O[nt][2] * iB; vec[baseB + 1] = O[nt][3] * iB;
    }
}

// ---------------- residual + LayerNorm ----------------
__global__ void ln_k(const float* __restrict__ w, const float* __restrict__ xb,
                     const float* __restrict__ g, const float* __restrict__ bb,
                     float* __restrict__ out) {
    __shared__ float smr[16];
    int row = blockIdx.x, t = threadIdx.x;
    const float* wr = w + (long long)row * 1024;
    const float* xr = xb + (long long)row * 1024;
    float loc[4], s = 0.f, sq = 0.f;
#pragma unroll
    for (int e = 0; e < 4; e++) {
        float x = wr[e * 256 + t] + xr[e * 256 + t];
        loc[e] = x; s += x; sq += x * x;
    }
#pragma unroll
    for (int o = 16; o; o >>= 1) {
        s += __shfl_xor_sync(0xffffffffu, s, o);
        sq += __shfl_xor_sync(0xffffffffu, sq, o);
    }
    if ((t & 31) == 0) { smr[t >> 5] = s; smr[8 + (t >> 5)] = sq; }
    __syncthreads();
    s = smr[t & 7]; sq = smr[8 + (t & 7)];
#pragma unroll
    for (int o = 4; o; o >>= 1) {
        s += __shfl_xor_sync(0xffffffffu, s, o);
        sq += __shfl_xor_sync(0xffffffffu, sq, o);
    }
    float mu = s * (1.0f / 1024.0f);
    float var = sq * (1.0f / 1024.0f) - mu * mu;
    float rstd = rsqrtf(var + EPS_F);
#pragma unroll
    for (int e = 0; e < 4; e++) {
        int c = e * 256 + t;
        out[(long long)row * 1024 + c] = (loc[e] - mu) * rstd * g[c] + bb[c];
    }
}

// ---------------- launch ----------------
extern "C" void kernel_launch(void* const* d_in, const int* in_sizes, int n_in,
                              void* d_out, int out_size) {
    const float* w    = (const float*)d_in[0];
    const float* r    = (const float*)d_in[1];
    const float* rwb  = (const float*)d_in[2];
    const float* rrb  = (const float*)d_in[3];
    const unsigned char* mask = (const unsigned char*)d_in[4];
    const float* Wqkv = (const float*)d_in[5];
    const float* Wrfw = (const float*)d_in[6];
    const float* Wrbw = (const float*)d_in[7];
    const float* Wo   = (const float*)d_in[8];
    const float* lng  = (const float*)d_in[9];
    const float* lnb  = (const float*)d_in[10];
    float* out = (float*)d_out;

    unsigned *q1u, *q2u, *kku, *rku;
    float *vv, *bd, *vec, *xb;
    cudaGetSymbolAddress((void**)&q1u, g_q1u);
    cudaGetSymbolAddress((void**)&q2u, g_q2u);
    cudaGetSymbolAddress((void**)&kku, g_kku);
    cudaGetSymbolAddress((void**)&vv, g_vv);
    cudaGetSymbolAddress((void**)&rku, g_rku);
    cudaGetSymbolAddress((void**)&bd, g_bd);
    cudaGetSymbolAddress((void**)&vec, g_vec);
    cudaGetSymbolAddress((void**)&xb, g_x);

    // zero pad row 2047 of rk (512 u32)
    zero_u<<<2, 256>>>(rku + 2047 * 512);

    // QKV GEMM (tf32) with fused head scatter -> q1u/q2u/kku bf16x2, vv fp32
    gemm_k<2><<<dim3(24, 16), 256>>>(w, Wqkv, nullptr, 1024, 1024, 3072, 0,
                                     nullptr, rwb, rrb, q1u, q2u, kku, vv);
    // merged r_fw (bx<8) + r_bw reversed (bx>=8) -> rku bf16x2
    gemm_k<3><<<dim3(16, 8), 256>>>(r, Wrfw, nullptr, 1024, 1024, 1024, 0,
                                    Wrbw, nullptr, nullptr,
                                    rku, rku + 2046 * 512, nullptr, nullptr);
    // BD band (bf16 MMA): 9 x 8 x 32
    bd_k<<<dim3(9, 8, 32), 256>>>(q2u, rku, bd);
    // fused AC + BD + mask + softmax + PV (bf16 MMA)
    int fl_smem = (4096 + 4096 + 3 * 2048) * 4 + (3 * 4096 + 1024) * 4;
    cudaFuncSetAttribute(flash_k, cudaFuncAttributeMaxDynamicSharedMemorySize, fl_smem);
    flash_k<<<dim3(8, 32), 256, fl_smem>>>(q1u, kku, vv, bd, mask, vec);
    // attn_out = vec @ W_o (tf32)
    gemm_k<0><<<dim3(8, 16), 256>>>(vec, Wo, xb, 1024, 1024, 1024, 1024,
                                    nullptr, nullptr, nullptr,
                                    nullptr, nullptr, nullptr, nullptr);
    // residual + LN
    ln_k<<<2048, 256>>>(w, xb, lng, lnb, out);
}

// round 9
// speedup vs baseline: 4.2943x; 1.0956x over previous
#include <cuda_runtime.h>
#include <cuda_bf16.h>
#include <math.h>

#define SCALE_F 0.125f
#define EPS_F 1e-5f

// ---------------- scratch (device globals) ----------------
__device__ unsigned g_q1u[32 * 1024 * 32];  // q + r_w_bias, bf16x2 [z][i][32]
__device__ unsigned g_q2u[32 * 1024 * 32];  // q + r_r_bias, bf16x2
__device__ unsigned g_kku[32 * 1024 * 32];  // k heads, bf16x2
__device__ float    g_vv[32 * 1024 * 64];   // v heads fp32 [z][i][64]
__device__ unsigned g_vvt[32 * 64 * 512];   // v transposed bf16x2 [z][d][j/2]
__device__ unsigned g_rku[2048 * 512];      // r_k bf16x2 [jr][512] (row 2047 zeroed)
__device__ __nv_bfloat16 g_bdh[67108864];   // BD bf16 [z][1024][2048] (band only)
__device__ float    g_vec[2048 * 1024];     // attn vec [(i*2+b)][n*64+d]
__device__ float    g_x[2048 * 1024];       // vec @ W_o

// ---------------- helpers ----------------
__device__ __forceinline__ void cp16(void* s, const void* g) {
    unsigned a = (unsigned)__cvta_generic_to_shared(s);
    asm volatile("cp.async.cg.shared.global [%0], [%1], 16;\n" ::"r"(a), "l"(g));
}
__device__ __forceinline__ unsigned packbf(float lo, float hi) {
    unsigned u;
    asm("cvt.rn.bf16x2.f32 %0, %1, %2;" : "=r"(u) : "f"(hi), "f"(lo));
    return u;
}
__device__ __forceinline__ int swzA(int r, int col) {  // 16-float rows (tf32 A)
    return r * 16 + (((col >> 2) ^ ((r >> 1) & 3)) << 2) + (col & 3);
}
__device__ __forceinline__ int swzB(int k, int n) {    // 64-float rows (fp32 B)
    return k * 64 + (((n >> 2) ^ ((2 * k) & 15)) << 2) + (n & 3);
}
// bf16x2 rows of 32 u32 (=64 bf16), XOR swizzle
__device__ __forceinline__ int adru(int r, int c) {
    return r * 32 + (((c >> 2) ^ (r & 7)) << 2) + (c & 3);
}
#define MMA_TF32(c, a, b)                                                          \
    asm volatile(                                                                  \
        "mma.sync.aligned.m16n8k8.row.col.f32.tf32.tf32.f32 "                      \
        "{%0,%1,%2,%3},{%4,%5,%6,%7},{%8,%9},{%0,%1,%2,%3};"                       \
        : "+f"(c[0]), "+f"(c[1]), "+f"(c[2]), "+f"(c[3])                           \
        : "r"(a[0]), "r"(a[1]), "r"(a[2]), "r"(a[3]), "r"(b[0]), "r"(b[1]))
#define MMA_BF16(c, a, b)                                                          \
    asm volatile(                                                                  \
        "mma.sync.aligned.m16n8k16.row.col.f32.bf16.bf16.f32 "                     \
        "{%0,%1,%2,%3},{%4,%5,%6,%7},{%8,%9},{%0,%1,%2,%3};"                       \
        : "+f"(c[0]), "+f"(c[1]), "+f"(c[2]), "+f"(c[3])                           \
        : "r"(a[0]), "r"(a[1]), "r"(a[2]), "r"(a[3]), "r"(b[0]), "r"(b[1]))

// ---------------- tf32 GEMM 128x128 (A fp32, B fp32 [K][N]) ----------------
// EPI 0: fp32 store C.  EPI 2: QKV scatter.  EPI 3: rk bf16x2 (bx>=8 -> bw reversed).
template <int EPI>
__global__ __launch_bounds__(256, 1) void gemm_k(
    const float* __restrict__ A, const float* __restrict__ B, float* __restrict__ C,
    int K, int lda, int ldb, int ldc,
    const float* __restrict__ B2,
    const float* __restrict__ bias1, const float* __restrict__ bias2,
    unsigned* __restrict__ u1, unsigned* __restrict__ u2, unsigned* __restrict__ u3,
    float* __restrict__ f4) {
    __shared__ float sm[2 * 4096];
    int t = threadIdx.x, lane = t & 31, lq = lane & 3, lr = lane >> 2;
    int row0 = blockIdx.y * 128;
    int col0 = (EPI == 3) ? (blockIdx.x & 7) * 128 : blockIdx.x * 128;
    bool bw = (EPI == 3) && (blockIdx.x >= 8);
    if (bw) B = B2;
    int warp = t >> 5, wm = warp >> 1, wn = warp & 1;

    float acc[2][8][4] = {};

    auto load_tile = [&](int kt, int st) {
        float* sA = sm + st * 4096;
        float* sB = sA + 2048;
        int k0 = kt * 16;
#pragma unroll
        for (int e = 0; e < 2; e++) {
            int c = e * 256 + t, r = c >> 2, c4 = c & 3;
            cp16(sA + r * 16 + ((c4 ^ ((r >> 1) & 3)) << 2),
                 A + (long long)(row0 + r) * lda + k0 + (c4 << 2));
        }
#pragma unroll
        for (int e = 0; e < 2; e++) {
            int c = e * 256 + t, kr = c >> 5, n4 = c & 31, p = n4 >> 4, n4p = n4 & 15;
            cp16(sB + p * 1024 + kr * 64 + ((n4p ^ ((2 * kr) & 15)) << 2),
                 B + (long long)(k0 + kr) * ldb + col0 + (n4 << 2));
        }
        asm volatile("cp.async.commit_group;\n");
    };

    load_tile(0, 0);
    int KT = K >> 4;
    for (int kt = 0; kt < KT; kt++) {
        int st = kt & 1;
        if (kt + 1 < KT) {
            load_tile(kt + 1, st ^ 1);
            asm volatile("cp.async.wait_group 1;\n");
        } else {
            asm volatile("cp.async.wait_group 0;\n");
        }
        __syncthreads();
        float* sA = sm + st * 4096;
        float* sB = sA + 2048;
#pragma unroll
        for (int ks = 0; ks < 16; ks += 8) {
            unsigned af[2][4], bf[8][2];
#pragma unroll
            for (int mt = 0; mt < 2; mt++) {
                int r = wm * 32 + mt * 16 + lr;
                af[mt][0] = __float_as_uint(sA[swzA(r, ks + lq)]);
                af[mt][1] = __float_as_uint(sA[swzA(r + 8, ks + lq)]);
                af[mt][2] = __float_as_uint(sA[swzA(r, ks + 4 + lq)]);
                af[mt][3] = __float_as_uint(sA[swzA(r + 8, ks + 4 + lq)]);
            }
#pragma unroll
            for (int nt = 0; nt < 8; nt++) {
                int nn = wn * 64 + nt * 8 + lr;
                int p = nn >> 6, np = nn & 63;
                bf[nt][0] = __float_as_uint(sB[p * 1024 + swzB(ks + lq, np)]);
                bf[nt][1] = __float_as_uint(sB[p * 1024 + swzB(ks + 4 + lq, np)]);
            }
#pragma unroll
            for (int mt = 0; mt < 2; mt++)
#pragma unroll
                for (int nt = 0; nt < 8; nt++) MMA_TF32(acc[mt][nt], af[mt], bf[nt]);
        }
        __syncthreads();
    }

#pragma unroll
    for (int mt = 0; mt < 2; mt++)
#pragma unroll
        for (int nt = 0; nt < 8; nt++) {
            int r0 = row0 + wm * 32 + mt * 16 + lr;
            int cb = col0 + wn * 64 + nt * 8 + 2 * lq;
#pragma unroll
            for (int pe = 0; pe < 2; pe++) {
                int rr = r0 + pe * 8;
                float v0 = acc[mt][nt][pe * 2], v1 = acc[mt][nt][pe * 2 + 1];
                if (EPI == 0) {
                    C[(long long)rr * ldc + cb] = v0;
                    C[(long long)rr * ldc + cb + 1] = v1;
                } else if (EPI == 3) {
                    if (bw) {
                        if (rr == 1023) continue;  // fw owns rk row 1023
                        u2[(long long)rr * (-512) + (cb >> 1)] = packbf(v0, v1);
                    } else {
                        u1[(long long)rr * 512 + (cb >> 1)] = packbf(v0, v1);
                    }
                } else {  // EPI == 2: QKV scatter
                    int i = rr >> 1, bb = rr & 1;
                    int sec = cb >> 10, c1 = cb & 1023, n = c1 >> 6, d = c1 & 63;
                    int z = bb * 16 + n;
                    if (sec == 0) {
                        long long idx = ((long long)z << 15) + (i << 5) + (d >> 1);
                        u1[idx] = packbf(v0 + bias1[c1], v1 + bias1[c1 + 1]);
                        u2[idx] = packbf(v0 + bias2[c1], v1 + bias2[c1 + 1]);
                    } else if (sec == 1) {
                        u3[((long long)z << 15) + (i << 5) + (d >> 1)] = packbf(v0, v1);
                    } else {
                        long long idx = ((long long)z << 16) + (i << 6) + d;
                        f4[idx] = v0; f4[idx + 1] = v1;
                    }
                }
            }
        }
}

// ---------------- zero pad row (u32) ----------------
__global__ void zero_u(unsigned* p) { p[blockIdx.x * 256 + threadIdx.x] = 0u; }

// ---------------- V transpose: vv[z][j][d] fp32 -> vvt[z][d][j/2] bf16x2 ----------------
__global__ __launch_bounds__(256) void vt_k(const float* __restrict__ vv,
                                            unsigned* __restrict__ vvt) {
    __shared__ float ts[128][65];
    int t = threadIdx.x, z = blockIdx.y, j0 = blockIdx.x * 128;
    const float* Vz = vv + ((long long)z << 16);
#pragma unroll
    for (int e = 0; e < 8; e++) {
        int idx = e * 256 + t, r = idx >> 4, c4 = idx & 15;
        float4 v = *(const float4*)(Vz + (long long)(j0 + r) * 64 + c4 * 4);
        ts[r][c4 * 4] = v.x; ts[r][c4 * 4 + 1] = v.y;
        ts[r][c4 * 4 + 2] = v.z; ts[r][c4 * 4 + 3] = v.w;
    }
    __syncthreads();
#pragma unroll
    for (int e = 0; e < 16; e++) {
        int idx = e * 256 + t, d = idx >> 6, jp = idx & 63;
        vvt[((long long)z << 15) + (d << 9) + (j0 >> 1) + jp] =
            packbf(ts[jp * 2][d], ts[jp * 2 + 1][d]);
    }
}

// ---------------- bf16 BD band GEMM -> bf16 output ----------------
__global__ __launch_bounds__(256, 2) void bd_k(
    const unsigned* __restrict__ q2, const unsigned* __restrict__ rk,
    unsigned* __restrict__ bdu) {
    __shared__ unsigned su[2 * 4096];
    unsigned* sA = su;
    unsigned* sB = su + 4096;
    int t = threadIdx.x, lane = t & 31, lq = lane & 3, lr = lane >> 2;
    int z = blockIdx.z;
    const unsigned* Az = q2 + ((long long)z << 15);
    const unsigned* Bz = rk + (long long)(z & 15) * 32;
    unsigned* Cz = bdu + ((long long)z << 20);
    int row0 = blockIdx.y * 128;
    int col0 = 896 - row0 + blockIdx.x * 128;
    int warp = t >> 5, wm = warp >> 1, wn = warp & 1;

#pragma unroll
    for (int e = 0; e < 4; e++) {
        int c = e * 256 + t, r = c >> 3, c4 = c & 7;
        cp16(sA + r * 32 + ((c4 ^ (r & 7)) << 2), Az + (long long)(row0 + r) * 32 + c4 * 4);
        cp16(sB + r * 32 + ((c4 ^ (r & 7)) << 2), Bz + (long long)(col0 + r) * 512 + c4 * 4);
    }
    asm volatile("cp.async.commit_group;\ncp.async.wait_group 0;\n");
    __syncthreads();

    float acc[2][8][4] = {};
#pragma unroll
    for (int s = 0; s < 4; s++) {
        unsigned af[2][4], bf[8][2];
#pragma unroll
        for (int mt = 0; mt < 2; mt++) {
            int r = wm * 32 + mt * 16 + lr;
            af[mt][0] = sA[adru(r, s * 8 + lq)];
            af[mt][1] = sA[adru(r + 8, s * 8 + lq)];
            af[mt][2] = sA[adru(r, s * 8 + 4 + lq)];
            af[mt][3] = sA[adru(r + 8, s * 8 + 4 + lq)];
        }
#pragma unroll
        for (int nt = 0; nt < 8; nt++) {
            int nn = wn * 64 + nt * 8 + lr;
            bf[nt][0] = sB[adru(nn, s * 8 + lq)];
            bf[nt][1] = sB[adru(nn, s * 8 + 4 + lq)];
        }
#pragma unroll
        for (int mt = 0; mt < 2; mt++)
#pragma unroll
            for (int nt = 0; nt < 8; nt++) MMA_BF16(acc[mt][nt], af[mt], bf[nt]);
    }

#pragma unroll
    for (int mt = 0; mt < 2; mt++)
#pragma unroll
        for (int nt = 0; nt < 8; nt++) {
            int r0 = row0 + wm * 32 + mt * 16 + lr;
            int cb = col0 + wn * 64 + nt * 8 + 2 * lq;
#pragma unroll
            for (int pe = 0; pe < 2; pe++) {
                int rr = r0 + pe * 8;
                Cz[((rr << 11) + cb) >> 1] = packbf(acc[mt][nt][pe * 2], acc[mt][nt][pe * 2 + 1]);
            }
        }
}

// ---------------- flash (bf16): S = Q1·K^T + BD_band, mask, online softmax, P·V ----------------
__global__ __launch_bounds__(256, 2) void flash_k(
    const unsigned* __restrict__ q1, const unsigned* __restrict__ kk,
    const unsigned* __restrict__ vvt, const __nv_bfloat16* __restrict__ bdh,
    const unsigned char* __restrict__ mask, float* __restrict__ vec) {
    extern __shared__ unsigned fsu[];
    unsigned* sQ = fsu;                   // 128 x 32 u32
    unsigned* sP = sQ + 4096;             // 128 x 32 u32
    unsigned* sK = sP + 4096;             // 3 x 64 x 32 u32
    unsigned* sVt = sK + 3 * 2048;        // 3 x 64 x 32 u32 (rows = d)
    float* sMask = (float*)(sVt + 3 * 2048);  // 1024 flags

    int t = threadIdx.x, lane = t & 31, warp = t >> 5;
    int lq = lane & 3, lr = lane >> 2;
    int i0 = blockIdx.x * 128, z = blockIdx.y, b = z >> 4, nh = z & 15;
    const unsigned* Qz = q1 + ((long long)z << 15);
    const unsigned* Kz = kk + ((long long)z << 15);
    const unsigned* Vtz = vvt + ((long long)z << 15);
    const __nv_bfloat16* bdz = bdh + ((long long)z << 21);

    for (int e = t; e < 1024; e += 256) sMask[e] = mask[e * 2 + b] ? 1.0f : 0.0f;

#pragma unroll
    for (int e = 0; e < 4; e++) {
        int c = e * 256 + t, r = c >> 3, c4 = c & 7;
        cp16(sQ + r * 32 + ((c4 ^ (r & 7)) << 2), Qz + (long long)(i0 + r) * 32 + c4 * 4);
    }
    auto loadKV = [&](int jt, int bufi) {
        unsigned* dK = sK + bufi * 2048;
        unsigned* dV = sVt + bufi * 2048;
        int j0 = jt * 64;
#pragma unroll
        for (int e = 0; e < 2; e++) {
            int c = e * 256 + t, r = c >> 3, c4 = c & 7;
            cp16(dK + r * 32 + ((c4 ^ (r & 7)) << 2), Kz + (long long)(j0 + r) * 32 + c4 * 4);
            // V^T tile: rows d (64), cols j-pairs (32 u32) starting at j0/2
            cp16(dV + r * 32 + ((c4 ^ (r & 7)) << 2),
                 Vtz + ((long long)r << 9) + (j0 >> 1) + c4 * 4);
        }
        asm volatile("cp.async.commit_group;\n");
    };
    loadKV(0, 0);
    loadKV(1, 1);

    float mA = -3.4e38f, mB = -3.4e38f, lA = 0.f, lB = 0.f;
    float O[8][4] = {};
    int rb = warp * 16 + lr;
    int rowA = i0 + rb;

    for (int jt = 0; jt < 16; jt++) {
        int buf = jt % 3;
        if (jt == 15) asm volatile("cp.async.wait_group 0;\n");
        else          asm volatile("cp.async.wait_group 1;\n");
        __syncthreads();

        // ---- S = Q1 @ K^T ----
        unsigned* cK = sK + buf * 2048;
        float S[8][4] = {};
#pragma unroll
        for (int s = 0; s < 4; s++) {
            unsigned a[4];
            a[0] = sQ[adru(rb, s * 8 + lq)];
            a[1] = sQ[adru(rb + 8, s * 8 + lq)];
            a[2] = sQ[adru(rb, s * 8 + 4 + lq)];
            a[3] = sQ[adru(rb + 8, s * 8 + 4 + lq)];
#pragma unroll
            for (int nt = 0; nt < 8; nt++) {
                int nn = nt * 8 + lr;
                unsigned bfx[2];
                bfx[0] = cK[adru(nn, s * 8 + lq)];
                bfx[1] = cK[adru(nn, s * 8 + 4 + lq)];
                MMA_BF16(S[nt], a, bfx);
            }
        }

        // ---- add BD band (bf16), scale, mask ----
        int j0 = jt * 64;
#pragma unroll
        for (int nt = 0; nt < 8; nt++) {
            int jc = j0 + nt * 8 + 2 * lq;
            const __nv_bfloat16* b0 = bdz + (long long)rowA * 2048 + (1023 - rowA + jc);
            const __nv_bfloat16* b1 = bdz + (long long)(rowA + 8) * 2048 + (1015 - rowA + jc);
            float s0 = (S[nt][0] + __bfloat162float(__ldg(b0))) * SCALE_F;
            float s1 = (S[nt][1] + __bfloat162float(__ldg(b0 + 1))) * SCALE_F;
            float s2 = (S[nt][2] + __bfloat162float(__ldg(b1))) * SCALE_F;
            float s3 = (S[nt][3] + __bfloat162float(__ldg(b1 + 1))) * SCALE_F;
            if (sMask[jc] != 0.f)     { s0 = -1e30f; s2 = -1e30f; }
            if (sMask[jc + 1] != 0.f) { s1 = -1e30f; s3 = -1e30f; }
            S[nt][0] = s0; S[nt][1] = s1; S[nt][2] = s2; S[nt][3] = s3;
        }

        // ---- online softmax ----
        float mxA = -3.4e38f, mxB = -3.4e38f;
#pragma unroll
        for (int nt = 0; nt < 8; nt++) {
            mxA = fmaxf(mxA, fmaxf(S[nt][0], S[nt][1]));
            mxB = fmaxf(mxB, fmaxf(S[nt][2], S[nt][3]));
        }
        mxA = fmaxf(mxA, __shfl_xor_sync(0xffffffffu, mxA, 1));
        mxA = fmaxf(mxA, __shfl_xor_sync(0xffffffffu, mxA, 2));
        mxB = fmaxf(mxB, __shfl_xor_sync(0xffffffffu, mxB, 1));
        mxB = fmaxf(mxB, __shfl_xor_sync(0xffffffffu, mxB, 2));
        float nmA = fmaxf(mA, mxA), nmB = fmaxf(mB, mxB);
        float scA = __expf(mA - nmA), scB = __expf(mB - nmB);
        mA = nmA; mB = nmB;
        float smA = 0.f, smB = 0.f;
#pragma unroll
        for (int nt = 0; nt < 8; nt++) {
            float p0 = __expf(S[nt][0] - nmA), p1 = __expf(S[nt][1] - nmA);
            float p2 = __expf(S[nt][2] - nmB), p3 = __expf(S[nt][3] - nmB);
            smA += p0 + p1; smB += p2 + p3;
            sP[adru(rb, nt * 4 + lq)] = packbf(p0, p1);
            sP[adru(rb + 8, nt * 4 + lq)] = packbf(p2, p3);
        }
        smA += __shfl_xor_sync(0xffffffffu, smA, 1);
        smA += __shfl_xor_sync(0xffffffffu, smA, 2);
        smB += __shfl_xor_sync(0xffffffffu, smB, 1);
        smB += __shfl_xor_sync(0xffffffffu, smB, 2);
        lA = lA * scA + smA;
        lB = lB * scB + smB;
#pragma unroll
        for (int nt = 0; nt < 8; nt++) {
            O[nt][0] *= scA; O[nt][1] *= scA;
            O[nt][2] *= scB; O[nt][3] *= scB;
        }
        __syncwarp();  // sP rows are warp-private

        // ---- O += P @ V (V^T tile: rows d, j-pairs packed — symmetric to K) ----
        unsigned* cV = sVt + buf * 2048;
#pragma unroll
        for (int s = 0; s < 4; s++) {
            unsigned a[4];
            a[0] = sP[adru(rb, s * 8 + lq)];
            a[1] = sP[adru(rb + 8, s * 8 + lq)];
            a[2] = sP[adru(rb, s * 8 + 4 + lq)];
            a[3] = sP[adru(rb + 8, s * 8 + 4 + lq)];
#pragma unroll
            for (int nt = 0; nt < 8; nt++) {
                int nn = nt * 8 + lr;
                unsigned bfx[2];
                bfx[0] = cV[adru(nn, s * 8 + lq)];
                bfx[1] = cV[adru(nn, s * 8 + 4 + lq)];
                MMA_BF16(O[nt], a, bfx);
            }
        }

        if (jt + 2 < 16) loadKV(jt + 2, (jt + 2) % 3);
    }

    float iA = 1.0f / lA, iB = 1.0f / lB;
#pragma unroll
    for (int nt = 0; nt < 8; nt++) {
        int d0 = nt * 8 + 2 * lq;
        long long baseA = (((long long)(rowA * 2 + b)) << 10) + nh * 64 + d0;
        long long baseB = (((long long)((rowA + 8) * 2 + b)) << 10) + nh * 64 + d0;
        vec[baseA] = O[nt][0] * iA; vec[baseA + 1] = O[nt][1] * iA;
        vec[baseB] = O[nt][2] * iB; vec[baseB + 1] = O[nt][3] * iB;
    }
}

// ---------------- residual + LayerNorm ----------------
__global__ void ln_k(const float* __restrict__ w, const float* __restrict__ xb,
                     const float* __restrict__ g, const float* __restrict__ bb,
                     float* __restrict__ out) {
    __shared__ float smr[16];
    int row = blockIdx.x, t = threadIdx.x;
    const float* wr = w + (long long)row * 1024;
    const float* xr = xb + (long long)row * 1024;
    float loc[4], s = 0.f, sq = 0.f;
#pragma unroll
    for (int e = 0; e < 4; e++) {
        float x = wr[e * 256 + t] + xr[e * 256 + t];
        loc[e] = x; s += x; sq += x * x;
    }
#pragma unroll
    for (int o = 16; o; o >>= 1) {
        s += __shfl_xor_sync(0xffffffffu, s, o);
        sq += __shfl_xor_sync(0xffffffffu, sq, o);
    }
    if ((t & 31) == 0) { smr[t >> 5] = s; smr[8 + (t >> 5)] = sq; }
    __syncthreads();
    s = smr[t & 7]; sq = smr[8 + (t & 7)];
#pragma unroll
    for (int o = 4; o; o >>= 1) {
        s += __shfl_xor_sync(0xffffffffu, s, o);
        sq += __shfl_xor_sync(0xffffffffu, sq, o);
    }
    float mu = s * (1.0f / 1024.0f);
    float var = sq * (1.0f / 1024.0f) - mu * mu;
    float rstd = rsqrtf(var + EPS_F);
#pragma unroll
    for (int e = 0; e < 4; e++) {
        int c = e * 256 + t;
        out[(long long)row * 1024 + c] = (loc[e] - mu) * rstd * g[c] + bb[c];
    }
}

// ---------------- launch ----------------
extern "C" void kernel_launch(void* const* d_in, const int* in_sizes, int n_in,
                              void* d_out, int out_size) {
    const float* w    = (const float*)d_in[0];
    const float* r    = (const float*)d_in[1];
    const float* rwb  = (const float*)d_in[2];
    const float* rrb  = (const float*)d_in[3];
    const unsigned char* mask = (const unsigned char*)d_in[4];
    const float* Wqkv = (const float*)d_in[5];
    const float* Wrfw = (const float*)d_in[6];
    const float* Wrbw = (const float*)d_in[7];
    const float* Wo   = (const float*)d_in[8];
    const float* lng  = (const float*)d_in[9];
    const float* lnb  = (const float*)d_in[10];
    float* out = (float*)d_out;

    unsigned *q1u, *q2u, *kku, *rku, *vvt;
    __nv_bfloat16* bdh;
    float *vv, *vec, *xb;
    cudaGetSymbolAddress((void**)&q1u, g_q1u);
    cudaGetSymbolAddress((void**)&q2u, g_q2u);
    cudaGetSymbolAddress((void**)&kku, g_kku);
    cudaGetSymbolAddress((void**)&vv, g_vv);
    cudaGetSymbolAddress((void**)&vvt, g_vvt);
    cudaGetSymbolAddress((void**)&rku, g_rku);
    cudaGetSymbolAddress((void**)&bdh, g_bdh);
    cudaGetSymbolAddress((void**)&vec, g_vec);
    cudaGetSymbolAddress((void**)&xb, g_x);

    zero_u<<<2, 256>>>(rku + 2047 * 512);

    // QKV GEMM (tf32) with fused head scatter -> q1u/q2u/kku bf16x2, vv fp32
    gemm_k<2><<<dim3(24, 16), 256>>>(w, Wqkv, nullptr, 1024, 1024, 3072, 0,
                                     nullptr, rwb, rrb, q1u, q2u, kku, vv);
    // merged r_fw (bx<8) + r_bw reversed (bx>=8) -> rku bf16x2
    gemm_k<3><<<dim3(16, 8), 256>>>(r, Wrfw, nullptr, 1024, 1024, 1024, 0,
                                    Wrbw, nullptr, nullptr,
                                    rku, rku + 2046 * 512, nullptr, nullptr);
    // V transpose -> bf16x2 [z][d][j/2]
    vt_k<<<dim3(8, 32), 256>>>(vv, vvt);
    // BD band (bf16 in, bf16 out)
    bd_k<<<dim3(9, 8, 32), 256>>>(q2u, rku, (unsigned*)bdh);
    // fused AC + BD + mask + softmax + PV
    int fl_smem = (4096 + 4096 + 3 * 2048 + 3 * 2048) * 4 + 1024 * 4;
    cudaFuncSetAttribute(flash_k, cudaFuncAttributeMaxDynamicSharedMemorySize, fl_smem);
    flash_k<<<dim3(8, 32), 256, fl_smem>>>(q1u, kku, vvt, bdh, mask, vec);
    // attn_out = vec @ W_o (tf32)
    gemm_k<0><<<dim3(8, 16), 256>>>(vec, Wo, xb, 1024, 1024, 1024, 1024,
                                    nullptr, nullptr, nullptr,
                                    nullptr, nullptr, nullptr, nullptr);
    // residual + LN
    ln_k<<<2048, 256>>>(w, xb, lng, lnb, out);
}

// round 10
// speedup vs baseline: 5.2010x; 1.2111x over previous
#include <cuda_runtime.h>
#include <cuda_bf16.h>
#include <math.h>

#define SCALE_F 0.125f
#define EPS_F 1e-5f

// ---------------- scratch (device globals) ----------------
__device__ unsigned g_wu[2048 * 512];       // w packed bf16x2 [row][k/2]
__device__ unsigned g_ru[1024 * 512];       // r packed bf16x2
__device__ unsigned g_WqkvT[3072 * 512];    // W_qkv^T bf16x2 [n][k/2]
__device__ unsigned g_WrfwT[1024 * 512];    // W_r_fw^T bf16x2
__device__ unsigned g_WrbwT[1024 * 512];    // W_r_bw^T bf16x2
__device__ unsigned g_q1u[32 * 1024 * 32];  // q + r_w_bias, bf16x2 [z][i][32]
__device__ unsigned g_q2u[32 * 1024 * 32];  // q + r_r_bias, bf16x2
__device__ unsigned g_kku[32 * 1024 * 32];  // k heads, bf16x2
__device__ float    g_vv[32 * 1024 * 64];   // v heads fp32 [z][i][64]
__device__ unsigned g_vvt[32 * 64 * 512];   // v transposed bf16x2 [z][d][j/2]
__device__ unsigned g_rku[2048 * 512];      // r_k bf16x2 [jr][512] (row 2047 zeroed)
__device__ __nv_bfloat16 g_bdh[67108864];   // BD bf16 [z][1024][2048] (band only)
__device__ float    g_vec[2048 * 1024];     // attn vec [(i*2+b)][n*64+d] fp32
__device__ float    g_x[2048 * 1024];       // vec @ W_o

// ---------------- helpers ----------------
__device__ __forceinline__ void cp16(void* s, const void* g) {
    unsigned a = (unsigned)__cvta_generic_to_shared(s);
    asm volatile("cp.async.cg.shared.global [%0], [%1], 16;\n" ::"r"(a), "l"(g));
}
__device__ __forceinline__ unsigned packbf(float lo, float hi) {
    unsigned u;
    asm("cvt.rn.bf16x2.f32 %0, %1, %2;" : "=r"(u) : "f"(hi), "f"(lo));
    return u;
}
__device__ __forceinline__ int swzA(int r, int col) {  // 16-float rows (tf32 A)
    return r * 16 + (((col >> 2) ^ ((r >> 1) & 3)) << 2) + (col & 3);
}
__device__ __forceinline__ int swzB(int k, int n) {    // 64-float rows (fp32 B)
    return k * 64 + (((n >> 2) ^ ((2 * k) & 15)) << 2) + (n & 3);
}
// bf16x2 rows of 32 u32 (=64 bf16), XOR swizzle
__device__ __forceinline__ int adru(int r, int c) {
    return r * 32 + (((c >> 2) ^ (r & 7)) << 2) + (c & 3);
}
#define MMA_TF32(c, a, b)                                                          \
    asm volatile(                                                                  \
        "mma.sync.aligned.m16n8k8.row.col.f32.tf32.tf32.f32 "                      \
        "{%0,%1,%2,%3},{%4,%5,%6,%7},{%8,%9},{%0,%1,%2,%3};"                       \
        : "+f"(c[0]), "+f"(c[1]), "+f"(c[2]), "+f"(c[3])                           \
        : "r"(a[0]), "r"(a[1]), "r"(a[2]), "r"(a[3]), "r"(b[0]), "r"(b[1]))
#define MMA_BF16(c, a, b)                                                          \
    asm volatile(                                                                  \
        "mma.sync.aligned.m16n8k16.row.col.f32.bf16.bf16.f32 "                     \
        "{%0,%1,%2,%3},{%4,%5,%6,%7},{%8,%9},{%0,%1,%2,%3};"                       \
        : "+f"(c[0]), "+f"(c[1]), "+f"(c[2]), "+f"(c[3])                           \
        : "r"(a[0]), "r"(a[1]), "r"(a[2]), "r"(a[3]), "r"(b[0]), "r"(b[1]))

// ---------------- conversion kernels ----------------
__global__ __launch_bounds__(256) void pack_k(const float* __restrict__ in,
                                              unsigned* __restrict__ out, int n2) {
    int i = blockIdx.x * 256 + threadIdx.x;
    if (i < n2) {
        float2 v = ((const float2*)in)[i];
        out[i] = packbf(v.x, v.y);
    }
}
// fp32 [K][N] -> u32 [N][K/2] (transpose + pack). out row stride 512 (K=1024).
__global__ __launch_bounds__(256) void packT_k(const float* __restrict__ in,
                                               unsigned* __restrict__ out, int N) {
    __shared__ float ts[64][65];
    int t = threadIdx.x, n0 = blockIdx.x * 64, k0 = blockIdx.y * 64;
#pragma unroll
    for (int e = 0; e < 16; e++) {
        int idx = e * 256 + t, kk = idx >> 6, nn = idx & 63;
        ts[kk][nn] = in[(long long)(k0 + kk) * N + n0 + nn];
    }
    __syncthreads();
#pragma unroll
    for (int e = 0; e < 8; e++) {
        int idx = e * 256 + t, nn = idx >> 5, kp = idx & 31;
        out[(long long)(n0 + nn) * 512 + (k0 >> 1) + kp] =
            packbf(ts[2 * kp][nn], ts[2 * kp + 1][nn]);
    }
}
__global__ void zero_u(unsigned* p) { p[blockIdx.x * 256 + threadIdx.x] = 0u; }

// ---------------- bf16 GEMM 128x128, both operands u32 [rows][k/2] ----------------
// EPI 2: QKV head scatter (q1/q2/kk bf16x2, vv fp32). EPI 3: rk (bx>=8 -> bw reversed).
template <int EPI>
__global__ __launch_bounds__(256, 2) void bgemm_k(
    const unsigned* __restrict__ A, const unsigned* __restrict__ B,
    int KU, int ldau, int ldbu,
    const unsigned* __restrict__ B2,
    const float* __restrict__ bias1, const float* __restrict__ bias2,
    unsigned* __restrict__ u1, unsigned* __restrict__ u2, unsigned* __restrict__ u3,
    float* __restrict__ f4) {
    extern __shared__ unsigned su[];
    int t = threadIdx.x, lane = t & 31, lq = lane & 3, lr = lane >> 2;
    int row0 = blockIdx.y * 128;
    int col0 = (EPI == 3) ? (blockIdx.x & 7) * 128 : blockIdx.x * 128;
    bool bw = (EPI == 3) && (blockIdx.x >= 8);
    if (bw) B = B2;
    int warp = t >> 5, wm = warp >> 1, wn = warp & 1;

    float acc[2][8][4] = {};

    auto load_tile = [&](int kt, int st) {
        unsigned* sA = su + st * 8192;
        unsigned* sB = sA + 4096;
        int k0 = kt * 32;
#pragma unroll
        for (int e = 0; e < 4; e++) {
            int c = e * 256 + t, r = c >> 3, c4 = c & 7;
            cp16(sA + r * 32 + ((c4 ^ (r & 7)) << 2),
                 A + (long long)(row0 + r) * ldau + k0 + c4 * 4);
            cp16(sB + r * 32 + ((c4 ^ (r & 7)) << 2),
                 B + (long long)(col0 + r) * ldbu + k0 + c4 * 4);
        }
        asm volatile("cp.async.commit_group;\n");
    };

    load_tile(0, 0);
    int KT = KU >> 5;
    for (int kt = 0; kt < KT; kt++) {
        int st = kt & 1;
        if (kt + 1 < KT) {
            load_tile(kt + 1, st ^ 1);
            asm volatile("cp.async.wait_group 1;\n");
        } else {
            asm volatile("cp.async.wait_group 0;\n");
        }
        __syncthreads();
        unsigned* sA = su + st * 8192;
        unsigned* sB = sA + 4096;
#pragma unroll
        for (int s = 0; s < 4; s++) {
            unsigned af[2][4], bf[8][2];
#pragma unroll
            for (int mt = 0; mt < 2; mt++) {
                int r = wm * 32 + mt * 16 + lr;
                af[mt][0] = sA[adru(r, s * 8 + lq)];
                af[mt][1] = sA[adru(r + 8, s * 8 + lq)];
                af[mt][2] = sA[adru(r, s * 8 + 4 + lq)];
                af[mt][3] = sA[adru(r + 8, s * 8 + 4 + lq)];
            }
#pragma unroll
            for (int nt = 0; nt < 8; nt++) {
                int nn = wn * 64 + nt * 8 + lr;
                bf[nt][0] = sB[adru(nn, s * 8 + lq)];
                bf[nt][1] = sB[adru(nn, s * 8 + 4 + lq)];
            }
#pragma unroll
            for (int mt = 0; mt < 2; mt++)
#pragma unroll
                for (int nt = 0; nt < 8; nt++) MMA_BF16(acc[mt][nt], af[mt], bf[nt]);
        }
        __syncthreads();
    }

#pragma unroll
    for (int mt = 0; mt < 2; mt++)
#pragma unroll
        for (int nt = 0; nt < 8; nt++) {
            int r0 = row0 + wm * 32 + mt * 16 + lr;
            int cb = col0 + wn * 64 + nt * 8 + 2 * lq;
#pragma unroll
            for (int pe = 0; pe < 2; pe++) {
                int rr = r0 + pe * 8;
                float v0 = acc[mt][nt][pe * 2], v1 = acc[mt][nt][pe * 2 + 1];
                if (EPI == 3) {
                    if (bw) {
                        if (rr == 1023) continue;  // fw owns rk row 1023
                        u2[(long long)rr * (-512) + (cb >> 1)] = packbf(v0, v1);
                    } else {
                        u1[(long long)rr * 512 + (cb >> 1)] = packbf(v0, v1);
                    }
                } else {  // EPI == 2: QKV scatter
                    int i = rr >> 1, bb = rr & 1;
                    int sec = cb >> 10, c1 = cb & 1023, n = c1 >> 6, d = c1 & 63;
                    int z = bb * 16 + n;
                    if (sec == 0) {
                        long long idx = ((long long)z << 15) + (i << 5) + (d >> 1);
                        u1[idx] = packbf(v0 + bias1[c1], v1 + bias1[c1 + 1]);
                        u2[idx] = packbf(v0 + bias2[c1], v1 + bias2[c1 + 1]);
                    } else if (sec == 1) {
                        u3[((long long)z << 15) + (i << 5) + (d >> 1)] = packbf(v0, v1);
                    } else {
                        long long idx = ((long long)z << 16) + (i << 6) + d;
                        f4[idx] = v0; f4[idx + 1] = v1;
                    }
                }
            }
        }
}

// ---------------- tf32 GEMM for Wo (A fp32, B fp32 [K][N], plain fp32 store) ----------------
__global__ __launch_bounds__(256, 1) void wo_k(
    const float* __restrict__ A, const float* __restrict__ B, float* __restrict__ C,
    int K, int lda, int ldb, int ldc) {
    __shared__ float sm[2 * 4096];
    int t = threadIdx.x, lane = t & 31, lq = lane & 3, lr = lane >> 2;
    int row0 = blockIdx.y * 128, col0 = blockIdx.x * 128;
    int warp = t >> 5, wm = warp >> 1, wn = warp & 1;

    float acc[2][8][4] = {};

    auto load_tile = [&](int kt, int st) {
        float* sA = sm + st * 4096;
        float* sB = sA + 2048;
        int k0 = kt * 16;
#pragma unroll
        for (int e = 0; e < 2; e++) {
            int c = e * 256 + t, r = c >> 2, c4 = c & 3;
            cp16(sA + r * 16 + ((c4 ^ ((r >> 1) & 3)) << 2),
                 A + (long long)(row0 + r) * lda + k0 + (c4 << 2));
        }
#pragma unroll
        for (int e = 0; e < 2; e++) {
            int c = e * 256 + t, kr = c >> 5, n4 = c & 31, p = n4 >> 4, n4p = n4 & 15;
            cp16(sB + p * 1024 + kr * 64 + ((n4p ^ ((2 * kr) & 15)) << 2),
                 B + (long long)(k0 + kr) * ldb + col0 + (n4 << 2));
        }
        asm volatile("cp.async.commit_group;\n");
    };

    load_tile(0, 0);
    int KT = K >> 4;
    for (int kt = 0; kt < KT; kt++) {
        int st = kt & 1;
        if (kt + 1 < KT) {
            load_tile(kt + 1, st ^ 1);
            asm volatile("cp.async.wait_group 1;\n");
        } else {
            asm volatile("cp.async.wait_group 0;\n");
        }
        __syncthreads();
        float* sA = sm + st * 4096;
        float* sB = sA + 2048;
#pragma unroll
        for (int ks = 0; ks < 16; ks += 8) {
            unsigned af[2][4], bf[8][2];
#pragma unroll
            for (int mt = 0; mt < 2; mt++) {
                int r = wm * 32 + mt * 16 + lr;
                af[mt][0] = __float_as_uint(sA[swzA(r, ks + lq)]);
                af[mt][1] = __float_as_uint(sA[swzA(r + 8, ks + lq)]);
                af[mt][2] = __float_as_uint(sA[swzA(r, ks + 4 + lq)]);
                af[mt][3] = __float_as_uint(sA[swzA(r + 8, ks + 4 + lq)]);
            }
#pragma unroll
            for (int nt = 0; nt < 8; nt++) {
                int nn = wn * 64 + nt * 8 + lr;
                int p = nn >> 6, np = nn & 63;
                bf[nt][0] = __float_as_uint(sB[p * 1024 + swzB(ks + lq, np)]);
                bf[nt][1] = __float_as_uint(sB[p * 1024 + swzB(ks + 4 + lq, np)]);
            }
#pragma unroll
            for (int mt = 0; mt < 2; mt++)
#pragma unroll
                for (int nt = 0; nt < 8; nt++) MMA_TF32(acc[mt][nt], af[mt], bf[nt]);
        }
        __syncthreads();
    }

#pragma unroll
    for (int mt = 0; mt < 2; mt++)
#pragma unroll
        for (int nt = 0; nt < 8; nt++) {
            int r0 = row0 + wm * 32 + mt * 16 + lr;
            int cb = col0 + wn * 64 + nt * 8 + 2 * lq;
#pragma unroll
            for (int pe = 0; pe < 2; pe++) {
                int rr = r0 + pe * 8;
                C[(long long)rr * ldc + cb] = acc[mt][nt][pe * 2];
                C[(long long)rr * ldc + cb + 1] = acc[mt][nt][pe * 2 + 1];
            }
        }
}

// ---------------- V transpose: vv[z][j][d] fp32 -> vvt[z][d][j/2] bf16x2 ----------------
__global__ __launch_bounds__(256) void vt_k(const float* __restrict__ vv,
                                            unsigned* __restrict__ vvt) {
    __shared__ float ts[128][65];
    int t = threadIdx.x, z = blockIdx.y, j0 = blockIdx.x * 128;
    const float* Vz = vv + ((long long)z << 16);
#pragma unroll
    for (int e = 0; e < 8; e++) {
        int idx = e * 256 + t, r = idx >> 4, c4 = idx & 15;
        float4 v = *(const float4*)(Vz + (long long)(j0 + r) * 64 + c4 * 4);
        ts[r][c4 * 4] = v.x; ts[r][c4 * 4 + 1] = v.y;
        ts[r][c4 * 4 + 2] = v.z; ts[r][c4 * 4 + 3] = v.w;
    }
    __syncthreads();
#pragma unroll
    for (int e = 0; e < 16; e++) {
        int idx = e * 256 + t, d = idx >> 6, jp = idx & 63;
        vvt[((long long)z << 15) + (d << 9) + (j0 >> 1) + jp] =
            packbf(ts[jp * 2][d], ts[jp * 2 + 1][d]);
    }
}

// ---------------- bf16 BD band GEMM -> bf16 output ----------------
__global__ __launch_bounds__(256, 2) void bd_k(
    const unsigned* __restrict__ q2, const unsigned* __restrict__ rk,
    unsigned* __restrict__ bdu) {
    __shared__ unsigned su[2 * 4096];
    unsigned* sA = su;
    unsigned* sB = su + 4096;
    int t = threadIdx.x, lane = t & 31, lq = lane & 3, lr = lane >> 2;
    int z = blockIdx.z;
    const unsigned* Az = q2 + ((long long)z << 15);
    const unsigned* Bz = rk + (long long)(z & 15) * 32;
    unsigned* Cz = bdu + ((long long)z << 20);
    int row0 = blockIdx.y * 128;
    int col0 = 896 - row0 + blockIdx.x * 128;
    int warp = t >> 5, wm = warp >> 1, wn = warp & 1;

#pragma unroll
    for (int e = 0; e < 4; e++) {
        int c = e * 256 + t, r = c >> 3, c4 = c & 7;
        cp16(sA + r * 32 + ((c4 ^ (r & 7)) << 2), Az + (long long)(row0 + r) * 32 + c4 * 4);
        cp16(sB + r * 32 + ((c4 ^ (r & 7)) << 2), Bz + (long long)(col0 + r) * 512 + c4 * 4);
    }
    asm volatile("cp.async.commit_group;\ncp.async.wait_group 0;\n");
    __syncthreads();

    float acc[2][8][4] = {};
#pragma unroll
    for (int s = 0; s < 4; s++) {
        unsigned af[2][4], bf[8][2];
#pragma unroll
        for (int mt = 0; mt < 2; mt++) {
            int r = wm * 32 + mt * 16 + lr;
            af[mt][0] = sA[adru(r, s * 8 + lq)];
            af[mt][1] = sA[adru(r + 8, s * 8 + lq)];
            af[mt][2] = sA[adru(r, s * 8 + 4 + lq)];
            af[mt][3] = sA[adru(r + 8, s * 8 + 4 + lq)];
        }
#pragma unroll
        for (int nt = 0; nt < 8; nt++) {
            int nn = wn * 64 + nt * 8 + lr;
            bf[nt][0] = sB[adru(nn, s * 8 + lq)];
            bf[nt][1] = sB[adru(nn, s * 8 + 4 + lq)];
        }
#pragma unroll
        for (int mt = 0; mt < 2; mt++)
#pragma unroll
            for (int nt = 0; nt < 8; nt++) MMA_BF16(acc[mt][nt], af[mt], bf[nt]);
    }

#pragma unroll
    for (int mt = 0; mt < 2; mt++)
#pragma unroll
        for (int nt = 0; nt < 8; nt++) {
            int r0 = row0 + wm * 32 + mt * 16 + lr;
            int cb = col0 + wn * 64 + nt * 8 + 2 * lq;
#pragma unroll
            for (int pe = 0; pe < 2; pe++) {
                int rr = r0 + pe * 8;
                Cz[((rr << 11) + cb) >> 1] = packbf(acc[mt][nt][pe * 2], acc[mt][nt][pe * 2 + 1]);
            }
        }
}

// ---------------- flash (bf16): S = Q1·K^T + BD_band, mask, online softmax, P·V ----------------
__global__ __launch_bounds__(256, 2) void flash_k(
    const unsigned* __restrict__ q1, const unsigned* __restrict__ kk,
    const unsigned* __restrict__ vvt, const __nv_bfloat16* __restrict__ bdh,
    const unsigned char* __restrict__ mask, float* __restrict__ vec) {
    extern __shared__ unsigned fsu[];
    unsigned* sQ = fsu;                   // 128 x 32 u32
    unsigned* sP = sQ + 4096;             // 128 x 32 u32
    unsigned* sK = sP + 4096;             // 3 x 64 x 32 u32
    unsigned* sVt = sK + 3 * 2048;        // 3 x 64 x 32 u32 (rows = d)
    float* sMask = (float*)(sVt + 3 * 2048);  // 1024 flags

    int t = threadIdx.x, lane = t & 31, warp = t >> 5;
    int lq = lane & 3, lr = lane >> 2;
    int i0 = blockIdx.x * 128, z = blockIdx.y, b = z >> 4, nh = z & 15;
    const unsigned* Qz = q1 + ((long long)z << 15);
    const unsigned* Kz = kk + ((long long)z << 15);
    const unsigned* Vtz = vvt + ((long long)z << 15);
    const __nv_bfloat16* bdz = bdh + ((long long)z << 21);

    for (int e = t; e < 1024; e += 256) sMask[e] = mask[e * 2 + b] ? 1.0f : 0.0f;

#pragma unroll
    for (int e = 0; e < 4; e++) {
        int c = e * 256 + t, r = c >> 3, c4 = c & 7;
        cp16(sQ + r * 32 + ((c4 ^ (r & 7)) << 2), Qz + (long long)(i0 + r) * 32 + c4 * 4);
    }
    auto loadKV = [&](int jt, int bufi) {
        unsigned* dK = sK + bufi * 2048;
        unsigned* dV = sVt + bufi * 2048;
        int j0 = jt * 64;
#pragma unroll
        for (int e = 0; e < 2; e++) {
            int c = e * 256 + t, r = c >> 3, c4 = c & 7;
            cp16(dK + r * 32 + ((c4 ^ (r & 7)) << 2), Kz + (long long)(j0 + r) * 32 + c4 * 4);
            cp16(dV + r * 32 + ((c4 ^ (r & 7)) << 2),
                 Vtz + ((long long)r << 9) + (j0 >> 1) + c4 * 4);
        }
        asm volatile("cp.async.commit_group;\n");
    };
    loadKV(0, 0);
    loadKV(1, 1);

    float mA = -3.4e38f, mB = -3.4e38f, lA = 0.f, lB = 0.f;
    float O[8][4] = {};
    int rb = warp * 16 + lr;
    int rowA = i0 + rb;

    for (int jt = 0; jt < 16; jt++) {
        int buf = jt % 3;
        if (jt == 15) asm volatile("cp.async.wait_group 0;\n");
        else          asm volatile("cp.async.wait_group 1;\n");
        __syncthreads();

        unsigned* cK = sK + buf * 2048;
        float S[8][4] = {};
#pragma unroll
        for (int s = 0; s < 4; s++) {
            unsigned a[4];
            a[0] = sQ[adru(rb, s * 8 + lq)];
            a[1] = sQ[adru(rb + 8, s * 8 + lq)];
            a[2] = sQ[adru(rb, s * 8 + 4 + lq)];
            a[3] = sQ[adru(rb + 8, s * 8 + 4 + lq)];
#pragma unroll
            for (int nt = 0; nt < 8; nt++) {
                int nn = nt * 8 + lr;
                unsigned bfx[2];
                bfx[0] = cK[adru(nn, s * 8 + lq)];
                bfx[1] = cK[adru(nn, s * 8 + 4 + lq)];
                MMA_BF16(S[nt], a, bfx);
            }
        }

        int j0 = jt * 64;
#pragma unroll
        for (int nt = 0; nt < 8; nt++) {
            int jc = j0 + nt * 8 + 2 * lq;
            const __nv_bfloat16* b0 = bdz + (long long)rowA * 2048 + (1023 - rowA + jc);
            const __nv_bfloat16* b1 = bdz + (long long)(rowA + 8) * 2048 + (1015 - rowA + jc);
            float s0 = (S[nt][0] + __bfloat162float(__ldg(b0))) * SCALE_F;
            float s1 = (S[nt][1] + __bfloat162float(__ldg(b0 + 1))) * SCALE_F;
            float s2 = (S[nt][2] + __bfloat162float(__ldg(b1))) * SCALE_F;
            float s3 = (S[nt][3] + __bfloat162float(__ldg(b1 + 1))) * SCALE_F;
            if (sMask[jc] != 0.f)     { s0 = -1e30f; s2 = -1e30f; }
            if (sMask[jc + 1] != 0.f) { s1 = -1e30f; s3 = -1e30f; }
            S[nt][0] = s0; S[nt][1] = s1; S[nt][2] = s2; S[nt][3] = s3;
        }

        float mxA = -3.4e38f, mxB = -3.4e38f;
#pragma unroll
        for (int nt = 0; nt < 8; nt++) {
            mxA = fmaxf(mxA, fmaxf(S[nt][0], S[nt][1]));
            mxB = fmaxf(mxB, fmaxf(S[nt][2], S[nt][3]));
        }
        mxA = fmaxf(mxA, __shfl_xor_sync(0xffffffffu, mxA, 1));
        mxA = fmaxf(mxA, __shfl_xor_sync(0xffffffffu, mxA, 2));
        mxB = fmaxf(mxB, __shfl_xor_sync(0xffffffffu, mxB, 1));
        mxB = fmaxf(mxB, __shfl_xor_sync(0xffffffffu, mxB, 2));
        float nmA = fmaxf(mA, mxA), nmB = fmaxf(mB, mxB);
        float scA = __expf(mA - nmA), scB = __expf(mB - nmB);
        mA = nmA; mB = nmB;
        float smA = 0.f, smB = 0.f;
#pragma unroll
        for (int nt = 0; nt < 8; nt++) {
            float p0 = __expf(S[nt][0] - nmA), p1 = __expf(S[nt][1] - nmA);
            float p2 = __expf(S[nt][2] - nmB), p3 = __expf(S[nt][3] - nmB);
            smA += p0 + p1; smB += p2 + p3;
            sP[adru(rb, nt * 4 + lq)] = packbf(p0, p1);
            sP[adru(rb + 8, nt * 4 + lq)] = packbf(p2, p3);
        }
        smA += __shfl_xor_sync(0xffffffffu, smA, 1);
        smA += __shfl_xor_sync(0xffffffffu, smA, 2);
        smB += __shfl_xor_sync(0xffffffffu, smB, 1);
        smB += __shfl_xor_sync(0xffffffffu, smB, 2);
        lA = lA * scA + smA;
        lB = lB * scB + smB;
#pragma unroll
        for (int nt = 0; nt < 8; nt++) {
            O[nt][0] *= scA; O[nt][1] *= scA;
            O[nt][2] *= scB; O[nt][3] *= scB;
        }
        __syncwarp();

        unsigned* cV = sVt + buf * 2048;
#pragma unroll
        for (int s = 0; s < 4; s++) {
            unsigned a[4];
            a[0] = sP[adru(rb, s * 8 + lq)];
            a[1] = sP[adru(rb + 8, s * 8 + lq)];
            a[2] = sP[adru(rb, s * 8 + 4 + lq)];
            a[3] = sP[adru(rb + 8, s * 8 + 4 + lq)];
#pragma unroll
            for (int nt = 0; nt < 8; nt++) {
                int nn = nt * 8 + lr;
                unsigned bfx[2];
                bfx[0] = cV[adru(nn, s * 8 + lq)];
                bfx[1] = cV[adru(nn, s * 8 + 4 + lq)];
                MMA_BF16(O[nt], a, bfx);
            }
        }

        if (jt + 2 < 16) loadKV(jt + 2, (jt + 2) % 3);
    }

    float iA = 1.0f / lA, iB = 1.0f / lB;
#pragma unroll
    for (int nt = 0; nt < 8; nt++) {
        int d0 = nt * 8 + 2 * lq;
        long long baseA = (((long long)(rowA * 2 + b)) << 10) + nh * 64 + d0;
        long long baseB = (((long long)((rowA + 8) * 2 + b)) << 10) + nh * 64 + d0;
        vec[baseA] = O[nt][0] * iA; vec[baseA + 1] = O[nt][1] * iA;
        vec[baseB] = O[nt][2] * iB; vec[baseB + 1] = O[nt][3] * iB;
    }
}

// ---------------- residual + LayerNorm ----------------
__global__ void ln_k(const float* __restrict__ w, const float* __restrict__ xb,
                     const float* __restrict__ g, const float* __restrict__ bb,
                     float* __restrict__ out) {
    __shared__ float smr[16];
    int row = blockIdx.x, t = threadIdx.x;
    const float* wr = w + (long long)row * 1024;
    const float* xr = xb + (long long)row * 1024;
    float loc[4], s = 0.f, sq = 0.f;
#pragma unroll
    for (int e = 0; e < 4; e++) {
        float x = wr[e * 256 + t] + xr[e * 256 + t];
        loc[e] = x; s += x; sq += x * x;
    }
#pragma unroll
    for (int o = 16; o; o >>= 1) {
        s += __shfl_xor_sync(0xffffffffu, s, o);
        sq += __shfl_xor_sync(0xffffffffu, sq, o);
    }
    if ((t & 31) == 0) { smr[t >> 5] = s; smr[8 + (t >> 5)] = sq; }
    __syncthreads();
    s = smr[t & 7]; sq = smr[8 + (t & 7)];
#pragma unroll
    for (int o = 4; o; o >>= 1) {
        s += __shfl_xor_sync(0xffffffffu, s, o);
        sq += __shfl_xor_sync(0xffffffffu, sq, o);
    }
    float mu = s * (1.0f / 1024.0f);
    float var = sq * (1.0f / 1024.0f) - mu * mu;
    float rstd = rsqrtf(var + EPS_F);
#pragma unroll
    for (int e = 0; e < 4; e++) {
        int c = e * 256 + t;
        out[(long long)row * 1024 + c] = (loc[e] - mu) * rstd * g[c] + bb[c];
    }
}

// ---------------- launch ----------------
extern "C" void kernel_launch(void* const* d_in, const int* in_sizes, int n_in,
                              void* d_out, int out_size) {
    const float* w    = (const float*)d_in[0];
    const float* r    = (const float*)d_in[1];
    const float* rwb  = (const float*)d_in[2];
    const float* rrb  = (const float*)d_in[3];
    const unsigned char* mask = (const unsigned char*)d_in[4];
    const float* Wqkv = (const float*)d_in[5];
    const float* Wrfw = (const float*)d_in[6];
    const float* Wrbw = (const float*)d_in[7];
    const float* Wo   = (const float*)d_in[8];
    const float* lng  = (const float*)d_in[9];
    const float* lnb  = (const float*)d_in[10];
    float* out = (float*)d_out;

    unsigned *wu, *ru, *WqkvT, *WrfwT, *WrbwT;
    unsigned *q1u, *q2u, *kku, *rku, *vvt;
    __nv_bfloat16* bdh;
    float *vv, *vec, *xb;
    cudaGetSymbolAddress((void**)&wu, g_wu);
    cudaGetSymbolAddress((void**)&ru, g_ru);
    cudaGetSymbolAddress((void**)&WqkvT, g_WqkvT);
    cudaGetSymbolAddress((void**)&WrfwT, g_WrfwT);
    cudaGetSymbolAddress((void**)&WrbwT, g_WrbwT);
    cudaGetSymbolAddress((void**)&q1u, g_q1u);
    cudaGetSymbolAddress((void**)&q2u, g_q2u);
    cudaGetSymbolAddress((void**)&kku, g_kku);
    cudaGetSymbolAddress((void**)&vv, g_vv);
    cudaGetSymbolAddress((void**)&vvt, g_vvt);
    cudaGetSymbolAddress((void**)&rku, g_rku);
    cudaGetSymbolAddress((void**)&bdh, g_bdh);
    cudaGetSymbolAddress((void**)&vec, g_vec);
    cudaGetSymbolAddress((void**)&xb, g_x);

    zero_u<<<2, 256>>>(rku + 2047 * 512);

    // pack inputs to bf16x2
    pack_k<<<4096, 256>>>(w, wu, 2048 * 512);
    pack_k<<<2048, 256>>>(r, ru, 1024 * 512);
    packT_k<<<dim3(48, 16), 256>>>(Wqkv, WqkvT, 3072);
    packT_k<<<dim3(16, 16), 256>>>(Wrfw, WrfwT, 1024);
    packT_k<<<dim3(16, 16), 256>>>(Wrbw, WrbwT, 1024);

    int bg_smem = 2 * 8192 * 4;  // 64 KB
    cudaFuncSetAttribute(bgemm_k<2>, cudaFuncAttributeMaxDynamicSharedMemorySize, bg_smem);
    cudaFuncSetAttribute(bgemm_k<3>, cudaFuncAttributeMaxDynamicSharedMemorySize, bg_smem);

    // QKV GEMM (bf16) with fused head scatter
    bgemm_k<2><<<dim3(24, 16), 256, bg_smem>>>(wu, WqkvT, 512, 512, 512,
                                               nullptr, rwb, rrb, q1u, q2u, kku, vv);
    // merged r_fw (bx<8) + r_bw reversed (bx>=8) -> rku
    bgemm_k<3><<<dim3(16, 8), 256, bg_smem>>>(ru, WrfwT, 512, 512, 512,
                                              WrbwT, nullptr, nullptr,
                                              rku, rku + 2046 * 512, nullptr, nullptr);
    // V transpose -> bf16x2 [z][d][j/2]
    vt_k<<<dim3(8, 32), 256>>>(vv, vvt);
    // BD band
    bd_k<<<dim3(9, 8, 32), 256>>>(q2u, rku, (unsigned*)bdh);
    // fused AC + BD + mask + softmax + PV
    int fl_smem = (4096 + 4096 + 3 * 2048 + 3 * 2048) * 4 + 1024 * 4;
    cudaFuncSetAttribute(flash_k, cudaFuncAttributeMaxDynamicSharedMemorySize, fl_smem);
    flash_k<<<dim3(8, 32), 256, fl_smem>>>(q1u, kku, vvt, bdh, mask, vec);
    // attn_out = vec @ W_o (tf32, fp32 inputs — precision-critical path)
    wo_k<<<dim3(8, 16), 256>>>(vec, Wo, xb, 1024, 1024, 1024, 1024);
    // residual + LN
    ln_k<<<2048, 256>>>(w, xb, lng, lnb, out);
}